// round 1
// baseline (speedup 1.0000x reference)
#include <cuda_runtime.h>
#include <math.h>

#define NB 2
#define NT 2048
#define NC 1024
#define NH 16
#define DHD 64
#define NHID 32
#define N3C 3072
#define NM 4096          // NB*NT
#define NDIST 4095       // 2*NT-1

// ---------------- scratch (static device globals; no allocation) ----------------
__device__ __align__(16) float g_qT[NB*NH*DHD*NT];   // [B,H,Dh,T]
__device__ __align__(16) float g_kT[NB*NH*DHD*NT];   // [B,H,Dh,T]
__device__ __align__(16) float g_v [NB*NH*NT*DHD];   // [B,H,T,Dh]
__device__ __align__(16) float g_ctx[NM*NC];         // [B,T,C]
__device__ float g_bias[NH*NDIST];                   // [H, 2T-1]

// ---------------- fast exp on the FMA pipe (avoids MUFU throughput floor) -------
__device__ __forceinline__ float fast_exp(float x) {
    // exp(x) = 2^(x*log2e); x <= 0 here. Clamp to avoid exponent underflow.
    float t = x * 1.4426950408889634f;
    t = fmaxf(t, -126.0f);
    float r = rintf(t);
    float f = t - r;
    // Taylor for 2^f = sum (f ln2)^k/k!, |f|<=0.5, rel err ~1e-7
    float p = 1.5403530393381606e-4f;
    p = fmaf(p, f, 1.3333558146428443e-3f);
    p = fmaf(p, f, 9.618129107628477e-3f);
    p = fmaf(p, f, 5.550410866482158e-2f);
    p = fmaf(p, f, 2.402265069591007e-1f);
    p = fmaf(p, f, 6.931471805599453e-1f);
    p = fmaf(p, f, 1.0f);
    int e = (int)r;
    float s = __int_as_float((e + 127) << 23);
    return s * p;
}

// ---------------- RPE bias table: bias[h][d], d = (t-s)+T-1 --------------------
__global__ void rpe_kernel(const float* __restrict__ w1, const float* __restrict__ b1,
                           const float* __restrict__ w2, const float* __restrict__ b2)
{
    int d = blockIdx.x * blockDim.x + threadIdx.x;
    if (d >= NDIST) return;
    float rel = (float)(d - (NT - 1));
    float sgn = (rel > 0.f) ? 1.f : ((rel < 0.f) ? -1.f : 0.f);
    float x = sgn * log1pf(fabsf(rel));
    float h[NHID];
#pragma unroll
    for (int j = 0; j < NHID; j++)
        h[j] = fmaxf(fmaf(x, __ldg(&w1[j]), __ldg(&b1[j])), 0.f);
#pragma unroll
    for (int hd = 0; hd < NH; hd++) {
        float acc = __ldg(&b2[hd]);
#pragma unroll
        for (int j = 0; j < NHID; j++)
            acc = fmaf(h[j], __ldg(&w2[j*NH + hd]), acc);
        g_bias[hd*NDIST + d] = acc;
    }
}

// ---------------- shared SGEMM mainloop: 128x128 tile, BK=8, 8x8 micro ----------
__device__ __forceinline__ void gemm_tile(
    const float* __restrict__ A, const float* __restrict__ Bm,
    int K, int N, int bm, int bn, int tid,
    float* __restrict__ As, float* __restrict__ Bs, float acc[8][8])
{
    const int tx = tid & 15, ty = tid >> 4;
    const int arow = tid >> 1, acol = (tid & 1) * 4;
    const int brow = tid >> 5, bcol = (tid & 31) * 4;
    const float* Ap = A + (bm + arow) * K + acol;
    const float* Bp = Bm + brow * N + bn + bcol;

    for (int k0 = 0; k0 < K; k0 += 8) {
        float4 av = *(const float4*)(Ap + k0);
        float4 bv = *(const float4*)(Bp + (long)k0 * N);
        As[(acol+0)*132 + arow] = av.x;
        As[(acol+1)*132 + arow] = av.y;
        As[(acol+2)*132 + arow] = av.z;
        As[(acol+3)*132 + arow] = av.w;
        *(float4*)&Bs[brow*128 + bcol] = bv;
        __syncthreads();
#pragma unroll
        for (int kk = 0; kk < 8; kk++) {
            float4 a0 = *(const float4*)&As[kk*132 + ty*8];
            float4 a1 = *(const float4*)&As[kk*132 + ty*8 + 4];
            float4 b0 = *(const float4*)&Bs[kk*128 + tx*8];
            float4 b1 = *(const float4*)&Bs[kk*128 + tx*8 + 4];
            float a[8] = {a0.x,a0.y,a0.z,a0.w,a1.x,a1.y,a1.z,a1.w};
            float b[8] = {b0.x,b0.y,b0.z,b0.w,b1.x,b1.y,b1.z,b1.w};
#pragma unroll
            for (int i = 0; i < 8; i++)
#pragma unroll
                for (int j = 0; j < 8; j++)
                    acc[i][j] = fmaf(a[i], b[j], acc[i][j]);
        }
        __syncthreads();
    }
}

// ---------------- QKV projection, scattering into q/k (transposed) and v -------
__global__ void __launch_bounds__(256) qkv_gemm_kernel(
    const float* __restrict__ x, const float* __restrict__ w, const float* __restrict__ bias)
{
    __shared__ __align__(16) float As[8*132];
    __shared__ __align__(16) float Bs[8*128];
    float acc[8][8] = {};
    const int bm = blockIdx.y * 128, bn = blockIdx.x * 128;
    const int tid = threadIdx.x;
    gemm_tile(x, w, NC, N3C, bm, bn, tid, As, Bs, acc);
    const int tx = tid & 15, ty = tid >> 4;
#pragma unroll
    for (int i = 0; i < 8; i++) {
        int m = bm + ty*8 + i;
        int b = m >> 11, t = m & (NT-1);
#pragma unroll
        for (int j = 0; j < 8; j++) {
            int n = bn + tx*8 + j;
            float v = acc[i][j] + bias[n];
            int sel = n >> 10;
            int c = n & (NC-1);
            int head = c >> 6, dh = c & (DHD-1);
            int bh = b * NH + head;
            if (sel == 0)      g_qT[(bh*DHD + dh)*NT + t] = v;
            else if (sel == 1) g_kT[(bh*DHD + dh)*NT + t] = v;
            else               g_v [(bh*NT + t)*DHD + dh] = v;
        }
    }
}

// ---------------- output projection ---------------------------------------------
__global__ void __launch_bounds__(256) out_gemm_kernel(
    const float* __restrict__ w, const float* __restrict__ bias, float* __restrict__ out)
{
    __shared__ __align__(16) float As[8*132];
    __shared__ __align__(16) float Bs[8*128];
    float acc[8][8] = {};
    const int bm = blockIdx.y * 128, bn = blockIdx.x * 128;
    const int tid = threadIdx.x;
    gemm_tile(g_ctx, w, NC, NC, bm, bn, tid, As, Bs, acc);
    const int tx = tid & 15, ty = tid >> 4;
#pragma unroll
    for (int i = 0; i < 8; i++) {
        int m = bm + ty*8 + i;
#pragma unroll
        for (int j4 = 0; j4 < 2; j4++) {
            int n = bn + tx*8 + j4*4;
            float4 ov;
            ov.x = acc[i][j4*4+0] + bias[n+0];
            ov.y = acc[i][j4*4+1] + bias[n+1];
            ov.z = acc[i][j4*4+2] + bias[n+2];
            ov.w = acc[i][j4*4+3] + bias[n+3];
            *(float4*)&out[(long)m*NC + n] = ov;
        }
    }
}

// ---------------- flash attention with RPE bias ----------------------------------
#define BQ 128
#define BS 64
#define FLASH_SMEM_FLOATS (64*132 + 64*68 + 64*64 + 128*68 + 192 + 3*128)
#define FLASH_SMEM_BYTES  (FLASH_SMEM_FLOATS * 4)

__global__ void __launch_bounds__(256, 2) flash_kernel()
{
    extern __shared__ __align__(16) float sm[];
    float* Qs     = sm;                 // [64][132]  (dh, r)   Q pre-scaled by 1/8
    float* Ks     = Qs + 64*132;        // [64][68]   (dh, s)
    float* Vs     = Ks + 64*68;         // [64][64]   (s, dh)
    float* Ss     = Vs + 64*64;         // [128][68]  scores -> probs
    float* bias_s = Ss + 128*68;        // [192] diagonal band
    float* mrow   = bias_s + 192;       // [128]
    float* lrow   = mrow + 128;         // [128]
    float* srow   = lrow + 128;         // [128] rescale factor

    const int tid = threadIdx.x;
    const int tx = tid & 15, ty = tid >> 4;   // cols tx*4.., rows ty*8..
    const int bh = blockIdx.y;
    const int h  = bh & (NH-1);
    const int q0 = blockIdx.x * BQ;
    const float* qbase = g_qT + bh * DHD * NT;
    const float* kbase = g_kT + bh * DHD * NT;
    const float* vbase = g_v  + bh * NT * DHD;

    // load Q tile (gmem already transposed [dh][t]) into Qs[dh][r], fold 1/sqrt(Dh)
#pragma unroll
    for (int it = 0; it < 8; it++) {
        int i  = tid + it * 256;          // 2048 float4 units
        int dh = i >> 5;
        int r4 = (i & 31) * 4;
        float4 qv = *(const float4*)&qbase[dh*NT + q0 + r4];
        qv.x *= 0.125f; qv.y *= 0.125f; qv.z *= 0.125f; qv.w *= 0.125f;
        *(float4*)&Qs[dh*132 + r4] = qv;
    }
    if (tid < 128) { mrow[tid] = -1e30f; lrow[tid] = 0.f; }

    float oacc[8][4] = {};

    for (int s0 = 0; s0 < NT; s0 += BS) {
        __syncthreads();     // all warps done with previous Ks/Vs/bias_s
        // load K (transposed layout) and V (natural)
#pragma unroll
        for (int it = 0; it < 4; it++) {
            int i   = tid + it * 256;     // 1024 float4 units
            int row = i >> 4;             // dh for K, s for V
            int c4  = (i & 15) * 4;
            float4 kv = *(const float4*)&kbase[row*NT + s0 + c4];
            *(float4*)&Ks[row*68 + c4] = kv;
            float4 vv = *(const float4*)&vbase[(s0 + row)*DHD + c4];
            *(float4*)&Vs[row*64 + c4] = vv;
        }
        if (tid < 191) {
            int d = (q0 - s0) + (tid - 63) + (NT - 1);
            d = max(0, min(2*NT - 2, d));
            bias_s[tid] = g_bias[h*NDIST + d];
        }
        __syncthreads();

        // S = (Q/8) K^T
        float sacc[8][4] = {};
#pragma unroll
        for (int k = 0; k < DHD; k++) {
            float4 a0 = *(const float4*)&Qs[k*132 + ty*8];
            float4 a1 = *(const float4*)&Qs[k*132 + ty*8 + 4];
            float4 b0 = *(const float4*)&Ks[k*68 + tx*4];
            float a[8] = {a0.x,a0.y,a0.z,a0.w,a1.x,a1.y,a1.z,a1.w};
            float b[4] = {b0.x,b0.y,b0.z,b0.w};
#pragma unroll
            for (int i = 0; i < 8; i++)
#pragma unroll
                for (int j = 0; j < 4; j++)
                    sacc[i][j] = fmaf(a[i], b[j], sacc[i][j]);
        }
        // + RPE bias band, write to Ss
#pragma unroll
        for (int i = 0; i < 8; i++) {
            int row = ty*8 + i;
            float4 sv;
            sv.x = sacc[i][0] + bias_s[row - (tx*4+0) + 63];
            sv.y = sacc[i][1] + bias_s[row - (tx*4+1) + 63];
            sv.z = sacc[i][2] + bias_s[row - (tx*4+2) + 63];
            sv.w = sacc[i][3] + bias_s[row - (tx*4+3) + 63];
            *(float4*)&Ss[row*68 + tx*4] = sv;
        }
        __syncwarp();   // rows wid*16..wid*16+15 are warp-local

        // online softmax (rows are warp-local: warp wid owns rows [wid*16, wid*16+16))
        const int wid = tid >> 5, lane = tid & 31;
#pragma unroll
        for (int rr = 0; rr < 16; rr++) {
            int r = wid * 16 + rr;
            float v0 = Ss[r*68 + lane];
            float v1 = Ss[r*68 + lane + 32];
            float mx = fmaxf(v0, v1);
#pragma unroll
            for (int off = 16; off > 0; off >>= 1)
                mx = fmaxf(mx, __shfl_xor_sync(0xffffffffu, mx, off));
            float mold = mrow[r];
            float mnew = fmaxf(mold, mx);
            float p0 = fast_exp(v0 - mnew);
            float p1 = fast_exp(v1 - mnew);
            Ss[r*68 + lane]      = p0;
            Ss[r*68 + lane + 32] = p1;
            float sum = p0 + p1;
#pragma unroll
            for (int off = 16; off > 0; off >>= 1)
                sum += __shfl_xor_sync(0xffffffffu, sum, off);
            if (lane == 0) {
                float scv = fast_exp(mold - mnew);
                lrow[r] = lrow[r] * scv + sum;
                mrow[r] = mnew;
                srow[r] = scv;
            }
        }
        __syncwarp();

        // O = O*scale + P @ V
        float scv[8];
#pragma unroll
        for (int i = 0; i < 8; i++) scv[i] = srow[ty*8 + i];
#pragma unroll
        for (int i = 0; i < 8; i++)
#pragma unroll
            for (int j = 0; j < 4; j++) oacc[i][j] *= scv[i];
#pragma unroll
        for (int s = 0; s < BS; s++) {
            float4 vb = *(const float4*)&Vs[s*64 + tx*4];
#pragma unroll
            for (int i = 0; i < 8; i++) {
                float p = Ss[(ty*8 + i)*68 + s];
                oacc[i][0] = fmaf(p, vb.x, oacc[i][0]);
                oacc[i][1] = fmaf(p, vb.y, oacc[i][1]);
                oacc[i][2] = fmaf(p, vb.z, oacc[i][2]);
                oacc[i][3] = fmaf(p, vb.w, oacc[i][3]);
            }
        }
    }

    // normalize and write ctx[b][t][h*64 + col]
    const int b = bh >> 4;
#pragma unroll
    for (int i = 0; i < 8; i++) {
        int row = ty*8 + i;
        float inv = 1.f / lrow[row];
        float4 ov = { oacc[i][0]*inv, oacc[i][1]*inv, oacc[i][2]*inv, oacc[i][3]*inv };
        int t = q0 + row;
        *(float4*)&g_ctx[(b*NT + t)*NC + h*DHD + tx*4] = ov;
    }
}

// ---------------- launch ---------------------------------------------------------
extern "C" void kernel_launch(void* const* d_in, const int* in_sizes, int n_in,
                              void* d_out, int out_size)
{
    const float* x     = (const float*)d_in[0];
    const float* w_qkv = (const float*)d_in[1];
    const float* b_qkv = (const float*)d_in[2];
    const float* w_out = (const float*)d_in[3];
    const float* b_out = (const float*)d_in[4];
    const float* w1    = (const float*)d_in[5];
    const float* b1    = (const float*)d_in[6];
    const float* w2    = (const float*)d_in[7];
    const float* b2    = (const float*)d_in[8];
    float* out = (float*)d_out;

    cudaFuncSetAttribute(flash_kernel, cudaFuncAttributeMaxDynamicSharedMemorySize,
                         FLASH_SMEM_BYTES);

    rpe_kernel<<<(NDIST + 255) / 256, 256>>>(w1, b1, w2, b2);

    dim3 gq(N3C / 128, NM / 128);
    qkv_gemm_kernel<<<gq, 256>>>(x, w_qkv, b_qkv);

    dim3 gf(NT / BQ, NB * NH);
    flash_kernel<<<gf, 256, FLASH_SMEM_BYTES>>>();

    dim3 go(NC / 128, NM / 128);
    out_gemm_kernel<<<go, 256>>>(w_out, b_out, out);
}

// round 6
// speedup vs baseline: 1.3618x; 1.3618x over previous
#include <cuda_runtime.h>
#include <cuda_bf16.h>
#include <math.h>
#include <stdint.h>

#define NB 2
#define NT 2048
#define NC 1024
#define NH 16
#define DHD 64
#define NHID 32
#define N3C 3072
#define NM 4096          // NB*NT
#define NDIST 4095       // 2*NT-1
#define MMK 1024         // GEMM K depth
#define BM 128
#define BN 128
#define BKC 32           // K per chunk
#define NCHUNK (MMK/BKC) // 32

// ---------------- scratch (same static footprint as the PASSING R1 kernel) ------
__device__ __align__(16) float g_qT[NB*NH*DHD*NT];   // [B,H,Dh,T]
__device__ __align__(16) float g_kT[NB*NH*DHD*NT];   // [B,H,Dh,T]
__device__ __align__(16) float g_v [NB*NH*NT*DHD];   // [B,H,T,Dh]
__device__ __align__(16) float g_ctx[NM*NC];         // [B,T,C]
__device__ float g_bias[NH*NDIST];                   // [H, 2T-1]

// ================= PTX helpers (baseline ISA, compiles at sm_100) ===============
__device__ __forceinline__ uint32_t s2u(const void* p) {
    uint32_t a;
    asm("{ .reg .u64 t; cvta.to.shared.u64 t, %1; cvt.u32.u64 %0, t; }" : "=r"(a) : "l"(p));
    return a;
}
#define LDM_X4(r0,r1,r2,r3,addr) \
    asm volatile("ldmatrix.sync.aligned.m8n8.x4.shared.b16 {%0,%1,%2,%3}, [%4];" \
        : "=r"(r0),"=r"(r1),"=r"(r2),"=r"(r3) : "r"(addr))
#define LDM_X2T(r0,r1,addr) \
    asm volatile("ldmatrix.sync.aligned.m8n8.x2.trans.shared.b16 {%0,%1}, [%2];" \
        : "=r"(r0),"=r"(r1) : "r"(addr))

// MMA as macro: accumulator elements bind as direct lvalues
#define MMA_BF16(c0,c1,c2,c3,a0,a1,a2,a3,b0,b1) \
    asm volatile("mma.sync.aligned.m16n8k16.row.col.f32.bf16.bf16.f32 " \
                 "{%0,%1,%2,%3}, {%4,%5,%6,%7}, {%8,%9}, {%0,%1,%2,%3};" \
                 : "+f"(c0), "+f"(c1), "+f"(c2), "+f"(c3) \
                 : "r"(a0), "r"(a1), "r"(a2), "r"(a3), "r"(b0), "r"(b1))

// pack two floats -> bf16x2 (hi) and residual bf16x2 (lo)
#define CVT_HILO(x, y, hi, lo) do{ \
    asm("cvt.rn.bf16x2.f32 %0, %1, %2;" : "=r"(hi) : "f"(y), "f"(x)); \
    float _lx = (x) - __uint_as_float((hi) << 16); \
    float _ly = (y) - __uint_as_float((hi) & 0xFFFF0000u); \
    asm("cvt.rn.bf16x2.f32 %0, %1, %2;" : "=r"(lo) : "f"(_ly), "f"(_lx)); \
}while(0)

// ---------------- fast exp on the FMA pipe --------------------------------------
__device__ __forceinline__ float fast_exp(float x) {
    float t = x * 1.4426950408889634f;
    t = fmaxf(t, -126.0f);
    float r = rintf(t);
    float f = t - r;
    float p = 1.5403530393381606e-4f;
    p = fmaf(p, f, 1.3333558146428443e-3f);
    p = fmaf(p, f, 9.618129107628477e-3f);
    p = fmaf(p, f, 5.550410866482158e-2f);
    p = fmaf(p, f, 2.402265069591007e-1f);
    p = fmaf(p, f, 6.931471805599453e-1f);
    p = fmaf(p, f, 1.0f);
    int e = (int)r;
    float s = __int_as_float((e + 127) << 23);
    return s * p;
}

// ---------------- RPE bias table ------------------------------------------------
__global__ void rpe_kernel(const float* __restrict__ w1, const float* __restrict__ b1,
                           const float* __restrict__ w2, const float* __restrict__ b2)
{
    int d = blockIdx.x * blockDim.x + threadIdx.x;
    if (d >= NDIST) return;
    float rel = (float)(d - (NT - 1));
    float sgn = (rel > 0.f) ? 1.f : ((rel < 0.f) ? -1.f : 0.f);
    float x = sgn * log1pf(fabsf(rel));
    float h[NHID];
#pragma unroll
    for (int j = 0; j < NHID; j++)
        h[j] = fmaxf(fmaf(x, __ldg(&w1[j]), __ldg(&b1[j])), 0.f);
#pragma unroll
    for (int hd = 0; hd < NH; hd++) {
        float acc = __ldg(&b2[hd]);
#pragma unroll
        for (int j = 0; j < NHID; j++)
            acc = fmaf(h[j], __ldg(&w2[j*NH + hd]), acc);
        g_bias[hd*NDIST + d] = acc;
    }
}

// ---------------- mma.sync bf16 3-term split GEMM, fp32 in, convert on the fly --
// C[M,Ntot] = A[M,1024](fp32) * B[1024,Ntot](fp32, row-major [K][N]) + bias
// MODE 0: A = x input, epilogue scatters q/k transposed + v
// MODE 1: A = g_ctx,   plain store to outp
#define RS_A 80                                // A row stride bytes (32 bf16 + pad)
#define A_TILE_B (128 * RS_A)                  // 10240
#define RS_B 272                               // B row stride bytes (128 bf16 + pad)
#define B_TILE_B (32 * RS_B)                   // 8704
#define STAGE_B (2*A_TILE_B + 2*B_TILE_B)      // 37888
#define OFF_AHI 0
#define OFF_ALO A_TILE_B
#define OFF_BHI (2*A_TILE_B)
#define OFF_BLO (2*A_TILE_B + B_TILE_B)
#define MM_SMEM_BYTES (2 * STAGE_B)            // 75776

template<int MODE>
__global__ void __launch_bounds__(256, 1) mm_kernel(
    const float* __restrict__ Ain, const float* __restrict__ Bin, int ldb,
    const float* __restrict__ bias, float* __restrict__ outp)
{
    extern __shared__ __align__(16) char dsm[];
    const float* __restrict__ Ap = (MODE == 0) ? Ain : g_ctx;

    const int tid = threadIdx.x;
    const int wid = tid >> 5, lane = tid & 31;
    const int bm = blockIdx.y * BM, bn = blockIdx.x * BN;
    const int wm = (wid & 1) * 64, wn = (wid >> 1) * 32;
    const uint32_t sbase = s2u(dsm);

    float acc[4][4][4];
#pragma unroll
    for (int mi = 0; mi < 4; mi++)
#pragma unroll
        for (int ni = 0; ni < 4; ni++)
#pragma unroll
            for (int r = 0; r < 4; r++) acc[mi][ni][r] = 0.f;

    // prefetch pointers: A rows (tid>>1), 16 floats at (tid&1)*16; B rows (tid>>3), 16 floats at (tid&7)*16
    const float* __restrict__ aptr = Ap + (long)(bm + (tid >> 1)) * MMK + (tid & 1) * 16;
    const float* __restrict__ bptr = Bin + (long)(tid >> 3) * ldb + bn + (tid & 7) * 16;

    float4 va0, va1, va2, va3, vb0, vb1, vb2, vb3;
#define LOADC(k0) do { \
    const float* _a = aptr + (k0); \
    va0 = *(const float4*)(_a + 0);  va1 = *(const float4*)(_a + 4); \
    va2 = *(const float4*)(_a + 8);  va3 = *(const float4*)(_a + 12); \
    const float* _b = bptr + (long)(k0) * ldb; \
    vb0 = *(const float4*)(_b + 0);  vb1 = *(const float4*)(_b + 4); \
    vb2 = *(const float4*)(_b + 8);  vb3 = *(const float4*)(_b + 12); \
} while(0)

    LOADC(0);

    const int laneA_row = lane & 15, laneA_half = (lane >> 4) * 16;
    const uint32_t laneB_row = (lane & 7) + ((lane >> 3) & 1) * 8;   // 0..15

    for (int i = 0; i < NCHUNK; i++) {
        const int buf = i & 1;
        char* sp = dsm + buf * STAGE_B;

        // ---- convert regs (chunk i) -> smem[buf] ----
        {
            char* pa = sp + (tid >> 1) * RS_A + (tid & 1) * 32;
            uint32_t h0,h1,h2,h3,h4,h5,h6,h7, l0,l1,l2,l3,l4,l5,l6,l7;
            CVT_HILO(va0.x, va0.y, h0, l0);  CVT_HILO(va0.z, va0.w, h1, l1);
            CVT_HILO(va1.x, va1.y, h2, l2);  CVT_HILO(va1.z, va1.w, h3, l3);
            CVT_HILO(va2.x, va2.y, h4, l4);  CVT_HILO(va2.z, va2.w, h5, l5);
            CVT_HILO(va3.x, va3.y, h6, l6);  CVT_HILO(va3.z, va3.w, h7, l7);
            *(uint4*)(pa + OFF_AHI +  0) = make_uint4(h0, h1, h2, h3);
            *(uint4*)(pa + OFF_AHI + 16) = make_uint4(h4, h5, h6, h7);
            *(uint4*)(pa + OFF_ALO +  0) = make_uint4(l0, l1, l2, l3);
            *(uint4*)(pa + OFF_ALO + 16) = make_uint4(l4, l5, l6, l7);
        }
        {
            char* pb = sp + (tid >> 3) * RS_B + (tid & 7) * 32;
            uint32_t h0,h1,h2,h3,h4,h5,h6,h7, l0,l1,l2,l3,l4,l5,l6,l7;
            CVT_HILO(vb0.x, vb0.y, h0, l0);  CVT_HILO(vb0.z, vb0.w, h1, l1);
            CVT_HILO(vb1.x, vb1.y, h2, l2);  CVT_HILO(vb1.z, vb1.w, h3, l3);
            CVT_HILO(vb2.x, vb2.y, h4, l4);  CVT_HILO(vb2.z, vb2.w, h5, l5);
            CVT_HILO(vb3.x, vb3.y, h6, l6);  CVT_HILO(vb3.z, vb3.w, h7, l7);
            *(uint4*)(pb + OFF_BHI +  0) = make_uint4(h0, h1, h2, h3);
            *(uint4*)(pb + OFF_BHI + 16) = make_uint4(h4, h5, h6, h7);
            *(uint4*)(pb + OFF_BLO +  0) = make_uint4(l0, l1, l2, l3);
            *(uint4*)(pb + OFF_BLO + 16) = make_uint4(l4, l5, l6, l7);
        }
        __syncthreads();

        // ---- prefetch chunk i+1 into regs (overlaps with MMA below) ----
        if (i + 1 < NCHUNK) LOADC((i + 1) * BKC);

        // ---- MMA over smem[buf] ----
        const uint32_t stb  = sbase + buf * STAGE_B;
        const uint32_t sAhi = stb + OFF_AHI;
        const uint32_t sAlo = stb + OFF_ALO;
        const uint32_t sBhi = stb + OFF_BHI;
        const uint32_t sBlo = stb + OFF_BLO;

#pragma unroll
        for (int kk = 0; kk < 2; kk++) {
            const uint32_t koffA = kk * 32;                  // bytes into A row
            const uint32_t browB = (kk * 16 + laneB_row) * RS_B;
            uint32_t bh0,bh1,bh2,bh3,bh4,bh5,bh6,bh7;
            uint32_t bl0,bl1,bl2,bl3,bl4,bl5,bl6,bl7;
            LDM_X2T(bh0, bh1, sBhi + browB + (wn + 0*8) * 2);
            LDM_X2T(bh2, bh3, sBhi + browB + (wn + 1*8) * 2);
            LDM_X2T(bh4, bh5, sBhi + browB + (wn + 2*8) * 2);
            LDM_X2T(bh6, bh7, sBhi + browB + (wn + 3*8) * 2);
            LDM_X2T(bl0, bl1, sBlo + browB + (wn + 0*8) * 2);
            LDM_X2T(bl2, bl3, sBlo + browB + (wn + 1*8) * 2);
            LDM_X2T(bl4, bl5, sBlo + browB + (wn + 2*8) * 2);
            LDM_X2T(bl6, bl7, sBlo + browB + (wn + 3*8) * 2);
#pragma unroll
            for (int mi = 0; mi < 4; mi++) {
                uint32_t a0, a1, a2, a3;
                uint32_t aa = sAhi + (wm + mi*16 + laneA_row) * RS_A + laneA_half + koffA;
                LDM_X4(a0, a1, a2, a3, aa);
                MMA_BF16(acc[mi][0][0],acc[mi][0][1],acc[mi][0][2],acc[mi][0][3], a0,a1,a2,a3, bh0,bh1);
                MMA_BF16(acc[mi][1][0],acc[mi][1][1],acc[mi][1][2],acc[mi][1][3], a0,a1,a2,a3, bh2,bh3);
                MMA_BF16(acc[mi][2][0],acc[mi][2][1],acc[mi][2][2],acc[mi][2][3], a0,a1,a2,a3, bh4,bh5);
                MMA_BF16(acc[mi][3][0],acc[mi][3][1],acc[mi][3][2],acc[mi][3][3], a0,a1,a2,a3, bh6,bh7);
                MMA_BF16(acc[mi][0][0],acc[mi][0][1],acc[mi][0][2],acc[mi][0][3], a0,a1,a2,a3, bl0,bl1);
                MMA_BF16(acc[mi][1][0],acc[mi][1][1],acc[mi][1][2],acc[mi][1][3], a0,a1,a2,a3, bl2,bl3);
                MMA_BF16(acc[mi][2][0],acc[mi][2][1],acc[mi][2][2],acc[mi][2][3], a0,a1,a2,a3, bl4,bl5);
                MMA_BF16(acc[mi][3][0],acc[mi][3][1],acc[mi][3][2],acc[mi][3][3], a0,a1,a2,a3, bl6,bl7);
            }
#pragma unroll
            for (int mi = 0; mi < 4; mi++) {
                uint32_t a0, a1, a2, a3;
                uint32_t aa = sAlo + (wm + mi*16 + laneA_row) * RS_A + laneA_half + koffA;
                LDM_X4(a0, a1, a2, a3, aa);
                MMA_BF16(acc[mi][0][0],acc[mi][0][1],acc[mi][0][2],acc[mi][0][3], a0,a1,a2,a3, bh0,bh1);
                MMA_BF16(acc[mi][1][0],acc[mi][1][1],acc[mi][1][2],acc[mi][1][3], a0,a1,a2,a3, bh2,bh3);
                MMA_BF16(acc[mi][2][0],acc[mi][2][1],acc[mi][2][2],acc[mi][2][3], a0,a1,a2,a3, bh4,bh5);
                MMA_BF16(acc[mi][3][0],acc[mi][3][1],acc[mi][3][2],acc[mi][3][3], a0,a1,a2,a3, bh6,bh7);
            }
        }
    }
#undef LOADC

    // ---- epilogue ----
    const int lane4 = lane >> 2, lane2 = (lane & 3) * 2;
#pragma unroll
    for (int mi = 0; mi < 4; mi++) {
        int r0 = bm + wm + mi*16 + lane4;
        int r1 = r0 + 8;
#pragma unroll
        for (int ni = 0; ni < 4; ni++) {
            int ng = bn + wn + ni*8 + lane2;
            float bz0 = bias[ng], bz1 = bias[ng + 1];
            float c0 = acc[mi][ni][0] + bz0, c1 = acc[mi][ni][1] + bz1;
            float c2 = acc[mi][ni][2] + bz0, c3 = acc[mi][ni][3] + bz1;
            if (MODE == 1) {
                float2 v0 = {c0, c1}, v1 = {c2, c3};
                *(float2*)&outp[(long)r0 * NC + ng] = v0;
                *(float2*)&outp[(long)r1 * NC + ng] = v1;
            } else {
                const int sel = bn >> 10;
                int n = ng & (NC - 1);
                int head = n >> 6, dh = n & (DHD - 1);
                int b0 = r0 >> 11, t0 = r0 & (NT - 1);
                int b1 = r1 >> 11, t1 = r1 & (NT - 1);
                if (sel == 2) {
                    float2 v0 = {c0, c1}, v1 = {c2, c3};
                    *(float2*)&g_v[(((b0 << 4) + head) * NT + t0) * DHD + dh] = v0;
                    *(float2*)&g_v[(((b1 << 4) + head) * NT + t1) * DHD + dh] = v1;
                } else {
                    float* dst = sel ? g_kT : g_qT;
                    dst[(((b0 << 4) + head) * DHD + dh    ) * NT + t0] = c0;
                    dst[(((b0 << 4) + head) * DHD + dh + 1) * NT + t0] = c1;
                    dst[(((b1 << 4) + head) * DHD + dh    ) * NT + t1] = c2;
                    dst[(((b1 << 4) + head) * DHD + dh + 1) * NT + t1] = c3;
                }
            }
        }
    }
}

// ---------------- flash attention with RPE bias (identical to passing R1) --------
#define BQ 128
#define BS 64
#define FLASH_SMEM_FLOATS (64*132 + 64*68 + 64*64 + 128*68 + 192 + 3*128)
#define FLASH_SMEM_BYTES  (FLASH_SMEM_FLOATS * 4)

__global__ void __launch_bounds__(256, 2) flash_kernel()
{
    extern __shared__ __align__(16) float sm[];
    float* Qs     = sm;                 // [64][132]  (dh, r)   Q pre-scaled by 1/8
    float* Ks     = Qs + 64*132;        // [64][68]   (dh, s)
    float* Vs     = Ks + 64*68;         // [64][64]   (s, dh)
    float* Ss     = Vs + 64*64;         // [128][68]  scores -> probs
    float* bias_s = Ss + 128*68;        // [192] diagonal band
    float* mrow   = bias_s + 192;       // [128]
    float* lrow   = mrow + 128;         // [128]
    float* srow   = lrow + 128;         // [128] rescale factor

    const int tid = threadIdx.x;
    const int tx = tid & 15, ty = tid >> 4;
    const int bh = blockIdx.y;
    const int h  = bh & (NH-1);
    const int q0 = blockIdx.x * BQ;
    const float* qbase = g_qT + bh * DHD * NT;
    const float* kbase = g_kT + bh * DHD * NT;
    const float* vbase = g_v  + bh * NT * DHD;

#pragma unroll
    for (int it = 0; it < 8; it++) {
        int i  = tid + it * 256;
        int dh = i >> 5;
        int r4 = (i & 31) * 4;
        float4 qv = *(const float4*)&qbase[dh*NT + q0 + r4];
        qv.x *= 0.125f; qv.y *= 0.125f; qv.z *= 0.125f; qv.w *= 0.125f;
        *(float4*)&Qs[dh*132 + r4] = qv;
    }
    if (tid < 128) { mrow[tid] = -1e30f; lrow[tid] = 0.f; }

    float oacc[8][4] = {};

    for (int s0 = 0; s0 < NT; s0 += BS) {
        __syncthreads();
#pragma unroll
        for (int it = 0; it < 4; it++) {
            int i   = tid + it * 256;
            int row = i >> 4;
            int c4  = (i & 15) * 4;
            float4 kv = *(const float4*)&kbase[row*NT + s0 + c4];
            *(float4*)&Ks[row*68 + c4] = kv;
            float4 vv = *(const float4*)&vbase[(s0 + row)*DHD + c4];
            *(float4*)&Vs[row*64 + c4] = vv;
        }
        if (tid < 191) {
            int d = (q0 - s0) + (tid - 63) + (NT - 1);
            d = max(0, min(2*NT - 2, d));
            bias_s[tid] = g_bias[h*NDIST + d];
        }
        __syncthreads();

        float sacc[8][4] = {};
#pragma unroll
        for (int k = 0; k < DHD; k++) {
            float4 a0 = *(const float4*)&Qs[k*132 + ty*8];
            float4 a1 = *(const float4*)&Qs[k*132 + ty*8 + 4];
            float4 b0 = *(const float4*)&Ks[k*68 + tx*4];
            float a[8] = {a0.x,a0.y,a0.z,a0.w,a1.x,a1.y,a1.z,a1.w};
            float b[4] = {b0.x,b0.y,b0.z,b0.w};
#pragma unroll
            for (int i = 0; i < 8; i++)
#pragma unroll
                for (int j = 0; j < 4; j++)
                    sacc[i][j] = fmaf(a[i], b[j], sacc[i][j]);
        }
#pragma unroll
        for (int i = 0; i < 8; i++) {
            int row = ty*8 + i;
            float4 sv;
            sv.x = sacc[i][0] + bias_s[row - (tx*4+0) + 63];
            sv.y = sacc[i][1] + bias_s[row - (tx*4+1) + 63];
            sv.z = sacc[i][2] + bias_s[row - (tx*4+2) + 63];
            sv.w = sacc[i][3] + bias_s[row - (tx*4+3) + 63];
            *(float4*)&Ss[row*68 + tx*4] = sv;
        }
        __syncwarp();

        const int wd = tid >> 5, lane = tid & 31;
#pragma unroll
        for (int rr = 0; rr < 16; rr++) {
            int r = wd * 16 + rr;
            float v0 = Ss[r*68 + lane];
            float v1 = Ss[r*68 + lane + 32];
            float mx = fmaxf(v0, v1);
#pragma unroll
            for (int off = 16; off > 0; off >>= 1)
                mx = fmaxf(mx, __shfl_xor_sync(0xffffffffu, mx, off));
            float mold = mrow[r];
            float mnew = fmaxf(mold, mx);
            float p0 = fast_exp(v0 - mnew);
            float p1 = fast_exp(v1 - mnew);
            Ss[r*68 + lane]      = p0;
            Ss[r*68 + lane + 32] = p1;
            float sum = p0 + p1;
#pragma unroll
            for (int off = 16; off > 0; off >>= 1)
                sum += __shfl_xor_sync(0xffffffffu, sum, off);
            if (lane == 0) {
                float scv = fast_exp(mold - mnew);
                lrow[r] = lrow[r] * scv + sum;
                mrow[r] = mnew;
                srow[r] = scv;
            }
        }
        __syncwarp();

        float scv[8];
#pragma unroll
        for (int i = 0; i < 8; i++) scv[i] = srow[ty*8 + i];
#pragma unroll
        for (int i = 0; i < 8; i++)
#pragma unroll
            for (int j = 0; j < 4; j++) oacc[i][j] *= scv[i];
#pragma unroll
        for (int s = 0; s < BS; s++) {
            float4 vb = *(const float4*)&Vs[s*64 + tx*4];
#pragma unroll
            for (int i = 0; i < 8; i++) {
                float p = Ss[(ty*8 + i)*68 + s];
                oacc[i][0] = fmaf(p, vb.x, oacc[i][0]);
                oacc[i][1] = fmaf(p, vb.y, oacc[i][1]);
                oacc[i][2] = fmaf(p, vb.z, oacc[i][2]);
                oacc[i][3] = fmaf(p, vb.w, oacc[i][3]);
            }
        }
    }

    // normalize and write ctx[b][t][h*64 + col] (fp32, as in R1)
    const int b = bh >> 4;
#pragma unroll
    for (int i = 0; i < 8; i++) {
        int row = ty*8 + i;
        float inv = 1.f / lrow[row];
        float4 ov = { oacc[i][0]*inv, oacc[i][1]*inv, oacc[i][2]*inv, oacc[i][3]*inv };
        int t = q0 + row;
        *(float4*)&g_ctx[(b*NT + t)*NC + h*DHD + tx*4] = ov;
    }
}

// ---------------- launch ---------------------------------------------------------
extern "C" void kernel_launch(void* const* d_in, const int* in_sizes, int n_in,
                              void* d_out, int out_size)
{
    const float* x     = (const float*)d_in[0];
    const float* w_qkv = (const float*)d_in[1];
    const float* b_qkv = (const float*)d_in[2];
    const float* w_out = (const float*)d_in[3];
    const float* b_out = (const float*)d_in[4];
    const float* w1    = (const float*)d_in[5];
    const float* b1    = (const float*)d_in[6];
    const float* w2    = (const float*)d_in[7];
    const float* b2    = (const float*)d_in[8];
    float* out = (float*)d_out;

    cudaFuncSetAttribute(flash_kernel, cudaFuncAttributeMaxDynamicSharedMemorySize,
                         FLASH_SMEM_BYTES);
    cudaFuncSetAttribute(mm_kernel<0>, cudaFuncAttributeMaxDynamicSharedMemorySize,
                         MM_SMEM_BYTES);
    cudaFuncSetAttribute(mm_kernel<1>, cudaFuncAttributeMaxDynamicSharedMemorySize,
                         MM_SMEM_BYTES);

    rpe_kernel<<<(NDIST + 255) / 256, 256>>>(w1, b1, w2, b2);

    // QKV projection (tensor cores, on-the-fly bf16 split)
    {
        dim3 g(N3C / BN, NM / BM);
        mm_kernel<0><<<g, 256, MM_SMEM_BYTES>>>(x, w_qkv, N3C, b_qkv, nullptr);
    }

    // flash attention
    {
        dim3 gf(NT / BQ, NB * NH);
        flash_kernel<<<gf, 256, FLASH_SMEM_BYTES>>>();
    }

    // output projection (tensor cores, on-the-fly bf16 split)
    {
        dim3 g(NC / BN, NM / BM);
        mm_kernel<1><<<g, 256, MM_SMEM_BYTES>>>(nullptr, w_out, NC, b_out, out);
    }
}

// round 7
// speedup vs baseline: 2.4242x; 1.7802x over previous
#include <cuda_runtime.h>
#include <cuda_bf16.h>
#include <math.h>
#include <stdint.h>

#define NB 2
#define NT 2048
#define NC 1024
#define NH 16
#define DHD 64
#define NHID 32
#define N3C 3072
#define NM 4096
#define NDIST 4095
#define MMK 1024
#define BM 128
#define BN 128
#define BKC 32
#define NCHUNK (MMK/BKC)

// ---------------- statics: 6 bf16 qkv arrays + fp32 ctx = same 67.4MB as R1/R6 --
__device__ __align__(16) __nv_bfloat16 g_qhi[NB*NH*NT*DHD];  // [bh][t][dh], pre-scaled 1/8
__device__ __align__(16) __nv_bfloat16 g_qlo[NB*NH*NT*DHD];
__device__ __align__(16) __nv_bfloat16 g_khi[NB*NH*NT*DHD];
__device__ __align__(16) __nv_bfloat16 g_klo[NB*NH*NT*DHD];
__device__ __align__(16) __nv_bfloat16 g_vhi[NB*NH*NT*DHD];
__device__ __align__(16) __nv_bfloat16 g_vlo[NB*NH*NT*DHD];
__device__ __align__(16) float g_ctx[NM*NC];
__device__ float g_bias[NH*NDIST];

// ================= PTX helpers ==================================================
__device__ __forceinline__ uint32_t s2u(const void* p) {
    uint32_t a;
    asm("{ .reg .u64 t; cvta.to.shared.u64 t, %1; cvt.u32.u64 %0, t; }" : "=r"(a) : "l"(p));
    return a;
}
#define CP_ASYNC16(dst, src) \
    asm volatile("cp.async.cg.shared.global [%0], [%1], 16;" :: "r"(dst), "l"(src))
#define CP_COMMIT() asm volatile("cp.async.commit_group;" ::: "memory")
#define CP_WAIT0()  asm volatile("cp.async.wait_group 0;" ::: "memory")

#define LDM_X4(r0,r1,r2,r3,addr) \
    asm volatile("ldmatrix.sync.aligned.m8n8.x4.shared.b16 {%0,%1,%2,%3}, [%4];" \
        : "=r"(r0),"=r"(r1),"=r"(r2),"=r"(r3) : "r"(addr))
#define LDM_X2(r0,r1,addr) \
    asm volatile("ldmatrix.sync.aligned.m8n8.x2.shared.b16 {%0,%1}, [%2];" \
        : "=r"(r0),"=r"(r1) : "r"(addr))
#define LDM_X2T(r0,r1,addr) \
    asm volatile("ldmatrix.sync.aligned.m8n8.x2.trans.shared.b16 {%0,%1}, [%2];" \
        : "=r"(r0),"=r"(r1) : "r"(addr))

#define MMA_BF16(c0,c1,c2,c3,a0,a1,a2,a3,b0,b1) \
    asm volatile("mma.sync.aligned.m16n8k16.row.col.f32.bf16.bf16.f32 " \
                 "{%0,%1,%2,%3}, {%4,%5,%6,%7}, {%8,%9}, {%0,%1,%2,%3};" \
                 : "+f"(c0), "+f"(c1), "+f"(c2), "+f"(c3) \
                 : "r"(a0), "r"(a1), "r"(a2), "r"(a3), "r"(b0), "r"(b1))

// pack two floats -> bf16x2 hi + residual bf16x2 lo ( .x of pair = first arg )
#define CVT_HILO(x, y, hi, lo) do{ \
    asm("cvt.rn.bf16x2.f32 %0, %1, %2;" : "=r"(hi) : "f"(y), "f"(x)); \
    float _lx = (x) - __uint_as_float((hi) << 16); \
    float _ly = (y) - __uint_as_float((hi) & 0xFFFF0000u); \
    asm("cvt.rn.bf16x2.f32 %0, %1, %2;" : "=r"(lo) : "f"(_ly), "f"(_lx)); \
}while(0)

// ---------------- fast exp on the FMA pipe --------------------------------------
__device__ __forceinline__ float fast_exp(float x) {
    float t = x * 1.4426950408889634f;
    t = fmaxf(t, -126.0f);
    float r = rintf(t);
    float f = t - r;
    float p = 1.5403530393381606e-4f;
    p = fmaf(p, f, 1.3333558146428443e-3f);
    p = fmaf(p, f, 9.618129107628477e-3f);
    p = fmaf(p, f, 5.550410866482158e-2f);
    p = fmaf(p, f, 2.402265069591007e-1f);
    p = fmaf(p, f, 6.931471805599453e-1f);
    p = fmaf(p, f, 1.0f);
    int e = (int)r;
    float s = __int_as_float((e + 127) << 23);
    return s * p;
}

// ---------------- RPE bias table ------------------------------------------------
__global__ void rpe_kernel(const float* __restrict__ w1, const float* __restrict__ b1,
                           const float* __restrict__ w2, const float* __restrict__ b2)
{
    int d = blockIdx.x * blockDim.x + threadIdx.x;
    if (d >= NDIST) return;
    float rel = (float)(d - (NT - 1));
    float sgn = (rel > 0.f) ? 1.f : ((rel < 0.f) ? -1.f : 0.f);
    float x = sgn * log1pf(fabsf(rel));
    float h[NHID];
#pragma unroll
    for (int j = 0; j < NHID; j++)
        h[j] = fmaxf(fmaf(x, __ldg(&w1[j]), __ldg(&b1[j])), 0.f);
#pragma unroll
    for (int hd = 0; hd < NH; hd++) {
        float acc = __ldg(&b2[hd]);
#pragma unroll
        for (int j = 0; j < NHID; j++)
            acc = fmaf(h[j], __ldg(&w2[j*NH + hd]), acc);
        g_bias[hd*NDIST + d] = acc;
    }
}

// ---------------- mma.sync bf16 3-term split GEMM (fp32 in, cvt on the fly) -----
#define RS_A 80
#define A_TILE_B (128 * RS_A)
#define RS_B 272
#define B_TILE_B (32 * RS_B)
#define STAGE_B (2*A_TILE_B + 2*B_TILE_B)
#define OFF_AHI 0
#define OFF_ALO A_TILE_B
#define OFF_BHI (2*A_TILE_B)
#define OFF_BLO (2*A_TILE_B + B_TILE_B)
#define MM_SMEM_BYTES (2 * STAGE_B)

template<int MODE>
__global__ void __launch_bounds__(256, 1) mm_kernel(
    const float* __restrict__ Ain, const float* __restrict__ Bin, int ldb,
    const float* __restrict__ bias, float* __restrict__ outp)
{
    extern __shared__ __align__(16) char dsm[];
    const float* __restrict__ Ap = (MODE == 0) ? Ain : g_ctx;

    const int tid = threadIdx.x;
    const int wid = tid >> 5, lane = tid & 31;
    const int bm = blockIdx.y * BM, bn = blockIdx.x * BN;
    const int wm = (wid & 1) * 64, wn = (wid >> 1) * 32;
    const uint32_t sbase = s2u(dsm);

    float acc[4][4][4];
#pragma unroll
    for (int mi = 0; mi < 4; mi++)
#pragma unroll
        for (int ni = 0; ni < 4; ni++)
#pragma unroll
            for (int r = 0; r < 4; r++) acc[mi][ni][r] = 0.f;

    const float* __restrict__ aptr = Ap + (long)(bm + (tid >> 1)) * MMK + (tid & 1) * 16;
    const float* __restrict__ bptr = Bin + (long)(tid >> 3) * ldb + bn + (tid & 7) * 16;

    float4 va0, va1, va2, va3, vb0, vb1, vb2, vb3;
#define LOADC(k0) do { \
    const float* _a = aptr + (k0); \
    va0 = *(const float4*)(_a + 0);  va1 = *(const float4*)(_a + 4); \
    va2 = *(const float4*)(_a + 8);  va3 = *(const float4*)(_a + 12); \
    const float* _b = bptr + (long)(k0) * ldb; \
    vb0 = *(const float4*)(_b + 0);  vb1 = *(const float4*)(_b + 4); \
    vb2 = *(const float4*)(_b + 8);  vb3 = *(const float4*)(_b + 12); \
} while(0)

    LOADC(0);

    const int laneA_row = lane & 15, laneA_half = (lane >> 4) * 16;
    const uint32_t laneB_row = (lane & 7) + ((lane >> 3) & 1) * 8;

    for (int i = 0; i < NCHUNK; i++) {
        const int buf = i & 1;
        char* sp = dsm + buf * STAGE_B;
        {
            char* pa = sp + (tid >> 1) * RS_A + (tid & 1) * 32;
            uint32_t h0,h1,h2,h3,h4,h5,h6,h7, l0,l1,l2,l3,l4,l5,l6,l7;
            CVT_HILO(va0.x, va0.y, h0, l0);  CVT_HILO(va0.z, va0.w, h1, l1);
            CVT_HILO(va1.x, va1.y, h2, l2);  CVT_HILO(va1.z, va1.w, h3, l3);
            CVT_HILO(va2.x, va2.y, h4, l4);  CVT_HILO(va2.z, va2.w, h5, l5);
            CVT_HILO(va3.x, va3.y, h6, l6);  CVT_HILO(va3.z, va3.w, h7, l7);
            *(uint4*)(pa + OFF_AHI +  0) = make_uint4(h0, h1, h2, h3);
            *(uint4*)(pa + OFF_AHI + 16) = make_uint4(h4, h5, h6, h7);
            *(uint4*)(pa + OFF_ALO +  0) = make_uint4(l0, l1, l2, l3);
            *(uint4*)(pa + OFF_ALO + 16) = make_uint4(l4, l5, l6, l7);
        }
        {
            char* pb = sp + (tid >> 3) * RS_B + (tid & 7) * 32;
            uint32_t h0,h1,h2,h3,h4,h5,h6,h7, l0,l1,l2,l3,l4,l5,l6,l7;
            CVT_HILO(vb0.x, vb0.y, h0, l0);  CVT_HILO(vb0.z, vb0.w, h1, l1);
            CVT_HILO(vb1.x, vb1.y, h2, l2);  CVT_HILO(vb1.z, vb1.w, h3, l3);
            CVT_HILO(vb2.x, vb2.y, h4, l4);  CVT_HILO(vb2.z, vb2.w, h5, l5);
            CVT_HILO(vb3.x, vb3.y, h6, l6);  CVT_HILO(vb3.z, vb3.w, h7, l7);
            *(uint4*)(pb + OFF_BHI +  0) = make_uint4(h0, h1, h2, h3);
            *(uint4*)(pb + OFF_BHI + 16) = make_uint4(h4, h5, h6, h7);
            *(uint4*)(pb + OFF_BLO +  0) = make_uint4(l0, l1, l2, l3);
            *(uint4*)(pb + OFF_BLO + 16) = make_uint4(l4, l5, l6, l7);
        }
        __syncthreads();

        if (i + 1 < NCHUNK) LOADC((i + 1) * BKC);

        const uint32_t stb  = sbase + buf * STAGE_B;
        const uint32_t sAhi = stb + OFF_AHI;
        const uint32_t sAlo = stb + OFF_ALO;
        const uint32_t sBhi = stb + OFF_BHI;
        const uint32_t sBlo = stb + OFF_BLO;

#pragma unroll
        for (int kk = 0; kk < 2; kk++) {
            const uint32_t koffA = kk * 32;
            const uint32_t browB = (kk * 16 + laneB_row) * RS_B;
            uint32_t bh0,bh1,bh2,bh3,bh4,bh5,bh6,bh7;
            uint32_t bl0,bl1,bl2,bl3,bl4,bl5,bl6,bl7;
            LDM_X2T(bh0, bh1, sBhi + browB + (wn + 0*8) * 2);
            LDM_X2T(bh2, bh3, sBhi + browB + (wn + 1*8) * 2);
            LDM_X2T(bh4, bh5, sBhi + browB + (wn + 2*8) * 2);
            LDM_X2T(bh6, bh7, sBhi + browB + (wn + 3*8) * 2);
            LDM_X2T(bl0, bl1, sBlo + browB + (wn + 0*8) * 2);
            LDM_X2T(bl2, bl3, sBlo + browB + (wn + 1*8) * 2);
            LDM_X2T(bl4, bl5, sBlo + browB + (wn + 2*8) * 2);
            LDM_X2T(bl6, bl7, sBlo + browB + (wn + 3*8) * 2);
#pragma unroll
            for (int mi = 0; mi < 4; mi++) {
                uint32_t a0, a1, a2, a3;
                uint32_t aa = sAhi + (wm + mi*16 + laneA_row) * RS_A + laneA_half + koffA;
                LDM_X4(a0, a1, a2, a3, aa);
                MMA_BF16(acc[mi][0][0],acc[mi][0][1],acc[mi][0][2],acc[mi][0][3], a0,a1,a2,a3, bh0,bh1);
                MMA_BF16(acc[mi][1][0],acc[mi][1][1],acc[mi][1][2],acc[mi][1][3], a0,a1,a2,a3, bh2,bh3);
                MMA_BF16(acc[mi][2][0],acc[mi][2][1],acc[mi][2][2],acc[mi][2][3], a0,a1,a2,a3, bh4,bh5);
                MMA_BF16(acc[mi][3][0],acc[mi][3][1],acc[mi][3][2],acc[mi][3][3], a0,a1,a2,a3, bh6,bh7);
                MMA_BF16(acc[mi][0][0],acc[mi][0][1],acc[mi][0][2],acc[mi][0][3], a0,a1,a2,a3, bl0,bl1);
                MMA_BF16(acc[mi][1][0],acc[mi][1][1],acc[mi][1][2],acc[mi][1][3], a0,a1,a2,a3, bl2,bl3);
                MMA_BF16(acc[mi][2][0],acc[mi][2][1],acc[mi][2][2],acc[mi][2][3], a0,a1,a2,a3, bl4,bl5);
                MMA_BF16(acc[mi][3][0],acc[mi][3][1],acc[mi][3][2],acc[mi][3][3], a0,a1,a2,a3, bl6,bl7);
            }
#pragma unroll
            for (int mi = 0; mi < 4; mi++) {
                uint32_t a0, a1, a2, a3;
                uint32_t aa = sAlo + (wm + mi*16 + laneA_row) * RS_A + laneA_half + koffA;
                LDM_X4(a0, a1, a2, a3, aa);
                MMA_BF16(acc[mi][0][0],acc[mi][0][1],acc[mi][0][2],acc[mi][0][3], a0,a1,a2,a3, bh0,bh1);
                MMA_BF16(acc[mi][1][0],acc[mi][1][1],acc[mi][1][2],acc[mi][1][3], a0,a1,a2,a3, bh2,bh3);
                MMA_BF16(acc[mi][2][0],acc[mi][2][1],acc[mi][2][2],acc[mi][2][3], a0,a1,a2,a3, bh4,bh5);
                MMA_BF16(acc[mi][3][0],acc[mi][3][1],acc[mi][3][2],acc[mi][3][3], a0,a1,a2,a3, bh6,bh7);
            }
        }
    }
#undef LOADC

    // ---- epilogue ----
    const int lane4 = lane >> 2, lane2 = (lane & 3) * 2;
#pragma unroll
    for (int mi = 0; mi < 4; mi++) {
        int r0 = bm + wm + mi*16 + lane4;
        int r1 = r0 + 8;
#pragma unroll
        for (int ni = 0; ni < 4; ni++) {
            int ng = bn + wn + ni*8 + lane2;
            float bz0 = bias[ng], bz1 = bias[ng + 1];
            float c0 = acc[mi][ni][0] + bz0, c1 = acc[mi][ni][1] + bz1;
            float c2 = acc[mi][ni][2] + bz0, c3 = acc[mi][ni][3] + bz1;
            if (MODE == 1) {
                float2 v0 = {c0, c1}, v1 = {c2, c3};
                *(float2*)&outp[(long)r0 * NC + ng] = v0;
                *(float2*)&outp[(long)r1 * NC + ng] = v1;
            } else {
                const int sel = bn >> 10;
                int n = ng & (NC - 1);
                int head = n >> 6, dh = n & (DHD - 1);
                int b0 = r0 >> 11, t0 = r0 & (NT - 1);
                int b1 = r1 >> 11, t1 = r1 & (NT - 1);
                if (sel == 0) { c0 *= 0.125f; c1 *= 0.125f; c2 *= 0.125f; c3 *= 0.125f; }
                uint32_t hi0, lo0, hi1, lo1;
                CVT_HILO(c0, c1, hi0, lo0);
                CVT_HILO(c2, c3, hi1, lo1);
                __nv_bfloat16* dhi = (sel == 0) ? g_qhi : (sel == 1) ? g_khi : g_vhi;
                __nv_bfloat16* dlo = (sel == 0) ? g_qlo : (sel == 1) ? g_klo : g_vlo;
                long e0 = ((long)(((b0 << 4) + head) * NT + t0)) * DHD + dh;
                long e1 = ((long)(((b1 << 4) + head) * NT + t1)) * DHD + dh;
                *(uint32_t*)(dhi + e0) = hi0;  *(uint32_t*)(dlo + e0) = lo0;
                *(uint32_t*)(dhi + e1) = hi1;  *(uint32_t*)(dlo + e1) = lo1;
            }
        }
    }
}

// ---------------- tensor-core flash attention with RPE bias ---------------------
// CTA: 128 q-rows, 8 warps (16 rows each, full 64-col width). s-tiles of 64.
#define RS_F 144                      // 128B row + 16B pad (conflict-free ldmatrix)
#define QTILE_B (128 * RS_F)          // 18432
#define KVT_B   (64 * RS_F)           // 9216
#define STAGE_F (4 * KVT_B)           // 36864 (khi,klo,vhi,vlo)
#define OFF_Q    0
#define OFF_ST   (2 * QTILE_B)        // 36864
#define OFF_BAND (OFF_ST + 2 * STAGE_F)  // 110592
#define FL_SMEM  (OFF_BAND + 2 * 192 * 8) // 113664

__global__ void __launch_bounds__(256, 1) flash_kernel()
{
    extern __shared__ __align__(16) char fsm[];
    const int tid = threadIdx.x, wid = tid >> 5, lane = tid & 31;
    const int bh = blockIdx.y, h = bh & (NH - 1), b = bh >> 4;
    const int q0 = blockIdx.x * 128;
    const uint32_t sb = s2u(fsm);
    const long kvbase = (long)bh * NT * DHD;
    const int hb = h * NDIST;
    float2* bandp = (float2*)(fsm + OFF_BAND);

    // ---- load Q tile (hi/lo) to smem ----
    {
        int qa = tid >> 7;            // 0: hi, 1: lo
        int row = tid & 127;
        const uint4* src = (const uint4*)((qa ? g_qlo : g_qhi) + kvbase + (long)(q0 + row) * DHD);
        uint4* dst = (uint4*)(fsm + OFF_Q + qa * QTILE_B + row * RS_F);
#pragma unroll
        for (int j = 0; j < 8; j++) dst[j] = src[j];
    }

#define CP_STAGE(tile, buf) do { \
    int a_ = tid >> 6; int row_ = tid & 63; \
    const __nv_bfloat16* g_ = (a_ == 0) ? g_khi : (a_ == 1) ? g_klo : (a_ == 2) ? g_vhi : g_vlo; \
    const char* src_ = (const char*)(g_ + kvbase + (long)((tile) * 64 + row_) * DHD); \
    uint32_t dst_ = sb + OFF_ST + (buf) * STAGE_F + a_ * KVT_B + row_ * RS_F; \
    CP_ASYNC16(dst_ +   0, src_ +   0); CP_ASYNC16(dst_ +  16, src_ +  16); \
    CP_ASYNC16(dst_ +  32, src_ +  32); CP_ASYNC16(dst_ +  48, src_ +  48); \
    CP_ASYNC16(dst_ +  64, src_ +  64); CP_ASYNC16(dst_ +  80, src_ +  80); \
    CP_ASYNC16(dst_ +  96, src_ +  96); CP_ASYNC16(dst_ + 112, src_ + 112); \
} while(0)

#define BAND_W(tile, buf) do { \
    if (tid < 191) { \
        int base_ = q0 - (tile) * 64 + 1984; \
        int i1_ = base_ + tid - 1; if (i1_ < 0) i1_ = 0; \
        bandp[(buf) * 192 + tid] = make_float2(g_bias[hb + base_ + tid], g_bias[hb + i1_]); \
    } \
} while(0)

    CP_STAGE(0, 0);
    CP_COMMIT();
    BAND_W(0, 0);
    __syncthreads();

    // ---- Q A-fragments for this warp's 16 rows (live for whole kernel) ----
    uint32_t qhf[4][4], qlf[4][4];
    {
        const uint32_t qa = sb + OFF_Q + (wid * 16 + (lane & 15)) * RS_F + (lane >> 4) * 16;
#pragma unroll
        for (int kt = 0; kt < 4; kt++) {
            LDM_X4(qhf[kt][0], qhf[kt][1], qhf[kt][2], qhf[kt][3], qa + kt * 32);
            LDM_X4(qlf[kt][0], qlf[kt][1], qlf[kt][2], qlf[kt][3], qa + QTILE_B + kt * 32);
        }
    }

    float o[8][4];
#pragma unroll
    for (int nt = 0; nt < 8; nt++)
#pragma unroll
        for (int r = 0; r < 4; r++) o[nt][r] = 0.f;
    float m0 = -1e30f, m1 = -1e30f, l0 = 0.f, l1 = 0.f;

    const int g = lane >> 2, t2 = (lane & 3) * 2;
    const int r0l = wid * 16 + g;                   // local row (0..119)
    const int e0 = r0l + 63 - t2;                   // band idx base, even cols
    const uint32_t lbB = (lane & 7);                // non-trans B rows
    const uint32_t hbB = ((lane >> 3) & 1) * 16;    // non-trans B k-half bytes
    const uint32_t lbT = (lane & 7) + ((lane >> 3) & 1) * 8;  // trans B rows

    for (int i = 0; i < 32; i++) {
        const int buf = i & 1;
        CP_WAIT0();
        __syncthreads();
        if (i + 1 < 32) {
            CP_STAGE(i + 1, buf ^ 1);
            CP_COMMIT();
            BAND_W(i + 1, buf ^ 1);
        }

        const uint32_t stg  = sb + OFF_ST + buf * STAGE_F;
        const uint32_t sKhi = stg, sKlo = stg + KVT_B;
        const uint32_t sVhi = stg + 2 * KVT_B;

        // ---- S = (Q/8) K^T  (3-term bf16 split) ----
        float s[8][4];
#pragma unroll
        for (int nt = 0; nt < 8; nt++)
#pragma unroll
            for (int r = 0; r < 4; r++) s[nt][r] = 0.f;

#pragma unroll
        for (int kt = 0; kt < 4; kt++) {
#pragma unroll
            for (int half = 0; half < 2; half++) {
                uint32_t kh[4][2], kl[4][2];
#pragma unroll
                for (int nt = 0; nt < 4; nt++) {
                    uint32_t ad = sKhi + ((half * 4 + nt) * 8 + lbB) * RS_F + hbB + kt * 32;
                    LDM_X2(kh[nt][0], kh[nt][1], ad);
                    LDM_X2(kl[nt][0], kl[nt][1], ad + KVT_B);
                }
#pragma unroll
                for (int nt = 0; nt < 4; nt++) {
                    int sn = half * 4 + nt;
                    MMA_BF16(s[sn][0],s[sn][1],s[sn][2],s[sn][3],
                             qhf[kt][0],qhf[kt][1],qhf[kt][2],qhf[kt][3], kh[nt][0],kh[nt][1]);
                    MMA_BF16(s[sn][0],s[sn][1],s[sn][2],s[sn][3],
                             qhf[kt][0],qhf[kt][1],qhf[kt][2],qhf[kt][3], kl[nt][0],kl[nt][1]);
                    MMA_BF16(s[sn][0],s[sn][1],s[sn][2],s[sn][3],
                             qlf[kt][0],qlf[kt][1],qlf[kt][2],qlf[kt][3], kh[nt][0],kh[nt][1]);
                }
            }
        }

        // ---- bias + online softmax (all in registers) ----
        const float2* bd = bandp + buf * 192;
        float mx0 = -1e30f, mx1 = -1e30f;
#pragma unroll
        for (int nt = 0; nt < 8; nt++) {
            float2 b0v = bd[e0 - 8 * nt];
            float2 b1v = bd[e0 + 8 - 8 * nt];
            s[nt][0] += b0v.x;  s[nt][1] += b0v.y;
            s[nt][2] += b1v.x;  s[nt][3] += b1v.y;
            mx0 = fmaxf(mx0, fmaxf(s[nt][0], s[nt][1]));
            mx1 = fmaxf(mx1, fmaxf(s[nt][2], s[nt][3]));
        }
        mx0 = fmaxf(mx0, __shfl_xor_sync(0xffffffffu, mx0, 1));
        mx0 = fmaxf(mx0, __shfl_xor_sync(0xffffffffu, mx0, 2));
        mx1 = fmaxf(mx1, __shfl_xor_sync(0xffffffffu, mx1, 1));
        mx1 = fmaxf(mx1, __shfl_xor_sync(0xffffffffu, mx1, 2));
        float mn0 = fmaxf(m0, mx0), mn1 = fmaxf(m1, mx1);
        float sc0 = fast_exp(m0 - mn0), sc1 = fast_exp(m1 - mn1);
        float su0 = 0.f, su1 = 0.f;
#pragma unroll
        for (int nt = 0; nt < 8; nt++) {
            s[nt][0] = fast_exp(s[nt][0] - mn0);
            s[nt][1] = fast_exp(s[nt][1] - mn0);
            s[nt][2] = fast_exp(s[nt][2] - mn1);
            s[nt][3] = fast_exp(s[nt][3] - mn1);
            su0 += s[nt][0] + s[nt][1];
            su1 += s[nt][2] + s[nt][3];
        }
        su0 += __shfl_xor_sync(0xffffffffu, su0, 1);
        su0 += __shfl_xor_sync(0xffffffffu, su0, 2);
        su1 += __shfl_xor_sync(0xffffffffu, su1, 1);
        su1 += __shfl_xor_sync(0xffffffffu, su1, 2);
        l0 = l0 * sc0 + su0;  m0 = mn0;
        l1 = l1 * sc1 + su1;  m1 = mn1;
#pragma unroll
        for (int nt = 0; nt < 8; nt++) {
            o[nt][0] *= sc0; o[nt][1] *= sc0;
            o[nt][2] *= sc1; o[nt][3] *= sc1;
        }

        // ---- O += P V  (P repacked in registers, 3-term split) ----
#pragma unroll
        for (int st = 0; st < 4; st++) {
            uint32_t ph0, ph1, ph2, ph3, pl0, pl1, pl2, pl3;
            CVT_HILO(s[2*st][0],   s[2*st][1],   ph0, pl0);
            CVT_HILO(s[2*st][2],   s[2*st][3],   ph1, pl1);
            CVT_HILO(s[2*st+1][0], s[2*st+1][1], ph2, pl2);
            CVT_HILO(s[2*st+1][2], s[2*st+1][3], ph3, pl3);
#pragma unroll
            for (int half = 0; half < 2; half++) {
                uint32_t vh[4][2], vl[4][2];
#pragma unroll
                for (int nt = 0; nt < 4; nt++) {
                    uint32_t ad = sVhi + (st * 16 + lbT) * RS_F + (half * 4 + nt) * 16;
                    LDM_X2T(vh[nt][0], vh[nt][1], ad);
                    LDM_X2T(vl[nt][0], vl[nt][1], ad + KVT_B);
                }
#pragma unroll
                for (int nt = 0; nt < 4; nt++) {
                    int on = half * 4 + nt;
                    MMA_BF16(o[on][0],o[on][1],o[on][2],o[on][3],
                             ph0,ph1,ph2,ph3, vh[nt][0],vh[nt][1]);
                    MMA_BF16(o[on][0],o[on][1],o[on][2],o[on][3],
                             ph0,ph1,ph2,ph3, vl[nt][0],vl[nt][1]);
                    MMA_BF16(o[on][0],o[on][1],o[on][2],o[on][3],
                             pl0,pl1,pl2,pl3, vh[nt][0],vh[nt][1]);
                }
            }
        }
    }

    // ---- normalize + write ctx ----
    {
        float inv0 = 1.f / l0, inv1 = 1.f / l1;
        int t0 = q0 + r0l, t1 = t0 + 8;
        float* c0p = g_ctx + (long)(b * NT + t0) * NC + h * DHD + t2;
        float* c1p = g_ctx + (long)(b * NT + t1) * NC + h * DHD + t2;
#pragma unroll
        for (int nt = 0; nt < 8; nt++) {
            float2 w0 = {o[nt][0] * inv0, o[nt][1] * inv0};
            float2 w1 = {o[nt][2] * inv1, o[nt][3] * inv1};
            *(float2*)(c0p + nt * 8) = w0;
            *(float2*)(c1p + nt * 8) = w1;
        }
    }
#undef CP_STAGE
#undef BAND_W
}

// ---------------- launch ---------------------------------------------------------
extern "C" void kernel_launch(void* const* d_in, const int* in_sizes, int n_in,
                              void* d_out, int out_size)
{
    const float* x     = (const float*)d_in[0];
    const float* w_qkv = (const float*)d_in[1];
    const float* b_qkv = (const float*)d_in[2];
    const float* w_out = (const float*)d_in[3];
    const float* b_out = (const float*)d_in[4];
    const float* w1    = (const float*)d_in[5];
    const float* b1    = (const float*)d_in[6];
    const float* w2    = (const float*)d_in[7];
    const float* b2    = (const float*)d_in[8];
    float* out = (float*)d_out;

    cudaFuncSetAttribute(flash_kernel, cudaFuncAttributeMaxDynamicSharedMemorySize,
                         FL_SMEM);
    cudaFuncSetAttribute(mm_kernel<0>, cudaFuncAttributeMaxDynamicSharedMemorySize,
                         MM_SMEM_BYTES);
    cudaFuncSetAttribute(mm_kernel<1>, cudaFuncAttributeMaxDynamicSharedMemorySize,
                         MM_SMEM_BYTES);

    rpe_kernel<<<(NDIST + 255) / 256, 256>>>(w1, b1, w2, b2);

    {   // QKV projection
        dim3 gq(N3C / BN, NM / BM);
        mm_kernel<0><<<gq, 256, MM_SMEM_BYTES>>>(x, w_qkv, N3C, b_qkv, nullptr);
    }
    {   // flash attention (tensor cores)
        dim3 gf(NT / 128, NB * NH);
        flash_kernel<<<gf, 256, FL_SMEM>>>();
    }
    {   // output projection
        dim3 go(NC / BN, NM / BM);
        mm_kernel<1><<<go, 256, MM_SMEM_BYTES>>>(nullptr, w_out, NC, b_out, out);
    }
}

// round 8
// speedup vs baseline: 2.6766x; 1.1041x over previous
#include <cuda_runtime.h>
#include <cuda_bf16.h>
#include <math.h>
#include <stdint.h>

#define NB 2
#define NT 2048
#define NC 1024
#define NH 16
#define DHD 64
#define NHID 32
#define N3C 3072
#define NM 4096
#define NDIST 4095
#define MMK 1024
#define BM 128
#define BN 128
#define BKC 32
#define NCHUNK (MMK/BKC)

// ---------------- statics: same 67.2MB footprint as passing R6/R7 ----------------
__device__ __align__(16) __nv_bfloat16 g_qhi[NB*NH*NT*DHD];  // [bh][t][dh], pre-scaled 1/8
__device__ __align__(16) __nv_bfloat16 g_qlo[NB*NH*NT*DHD];
__device__ __align__(16) __nv_bfloat16 g_khi[NB*NH*NT*DHD];
__device__ __align__(16) __nv_bfloat16 g_klo[NB*NH*NT*DHD];
__device__ __align__(16) __nv_bfloat16 g_vhi[NB*NH*NT*DHD];
__device__ __align__(16) __nv_bfloat16 g_vlo[NB*NH*NT*DHD];
__device__ __align__(16) float g_ctx[NM*NC];
__device__ float g_bias[NH*NDIST];

// ================= PTX helpers ==================================================
__device__ __forceinline__ uint32_t s2u(const void* p) {
    uint32_t a;
    asm("{ .reg .u64 t; cvta.to.shared.u64 t, %1; cvt.u32.u64 %0, t; }" : "=r"(a) : "l"(p));
    return a;
}
#define CP_ASYNC16(dst, src) \
    asm volatile("cp.async.cg.shared.global [%0], [%1], 16;" :: "r"(dst), "l"(src))
#define CP_COMMIT() asm volatile("cp.async.commit_group;" ::: "memory")
#define CP_WAIT0()  asm volatile("cp.async.wait_group 0;" ::: "memory")

#define LDM_X4(r0,r1,r2,r3,addr) \
    asm volatile("ldmatrix.sync.aligned.m8n8.x4.shared.b16 {%0,%1,%2,%3}, [%4];" \
        : "=r"(r0),"=r"(r1),"=r"(r2),"=r"(r3) : "r"(addr))
#define LDM_X4T(r0,r1,r2,r3,addr) \
    asm volatile("ldmatrix.sync.aligned.m8n8.x4.trans.shared.b16 {%0,%1,%2,%3}, [%4];" \
        : "=r"(r0),"=r"(r1),"=r"(r2),"=r"(r3) : "r"(addr))
#define LDM_X2T(r0,r1,addr) \
    asm volatile("ldmatrix.sync.aligned.m8n8.x2.trans.shared.b16 {%0,%1}, [%2];" \
        : "=r"(r0),"=r"(r1) : "r"(addr))

#define MMA_BF16(c0,c1,c2,c3,a0,a1,a2,a3,b0,b1) \
    asm volatile("mma.sync.aligned.m16n8k16.row.col.f32.bf16.bf16.f32 " \
                 "{%0,%1,%2,%3}, {%4,%5,%6,%7}, {%8,%9}, {%0,%1,%2,%3};" \
                 : "+f"(c0), "+f"(c1), "+f"(c2), "+f"(c3) \
                 : "r"(a0), "r"(a1), "r"(a2), "r"(a3), "r"(b0), "r"(b1))

#define CVT_HILO(x, y, hi, lo) do{ \
    asm("cvt.rn.bf16x2.f32 %0, %1, %2;" : "=r"(hi) : "f"(y), "f"(x)); \
    float _lx = (x) - __uint_as_float((hi) << 16); \
    float _ly = (y) - __uint_as_float((hi) & 0xFFFF0000u); \
    asm("cvt.rn.bf16x2.f32 %0, %1, %2;" : "=r"(lo) : "f"(_ly), "f"(_lx)); \
}while(0)

// ---------------- fast exp on the FMA pipe --------------------------------------
__device__ __forceinline__ float fast_exp(float x) {
    float t = x * 1.4426950408889634f;
    t = fmaxf(t, -126.0f);
    float r = rintf(t);
    float f = t - r;
    float p = 1.5403530393381606e-4f;
    p = fmaf(p, f, 1.3333558146428443e-3f);
    p = fmaf(p, f, 9.618129107628477e-3f);
    p = fmaf(p, f, 5.550410866482158e-2f);
    p = fmaf(p, f, 2.402265069591007e-1f);
    p = fmaf(p, f, 6.931471805599453e-1f);
    p = fmaf(p, f, 1.0f);
    int e = (int)r;
    float s = __int_as_float((e + 127) << 23);
    return s * p;
}

// ---------------- RPE bias table ------------------------------------------------
__global__ void rpe_kernel(const float* __restrict__ w1, const float* __restrict__ b1,
                           const float* __restrict__ w2, const float* __restrict__ b2)
{
    int d = blockIdx.x * blockDim.x + threadIdx.x;
    if (d >= NDIST) return;
    float rel = (float)(d - (NT - 1));
    float sgn = (rel > 0.f) ? 1.f : ((rel < 0.f) ? -1.f : 0.f);
    float x = sgn * log1pf(fabsf(rel));
    float h[NHID];
#pragma unroll
    for (int j = 0; j < NHID; j++)
        h[j] = fmaxf(fmaf(x, __ldg(&w1[j]), __ldg(&b1[j])), 0.f);
#pragma unroll
    for (int hd = 0; hd < NH; hd++) {
        float acc = __ldg(&b2[hd]);
#pragma unroll
        for (int j = 0; j < NHID; j++)
            acc = fmaf(h[j], __ldg(&w2[j*NH + hd]), acc);
        g_bias[hd*NDIST + d] = acc;
    }
}

// ---------------- mma.sync bf16 3-term split GEMM (unchanged from R7) -----------
#define RS_A 80
#define A_TILE_B (128 * RS_A)
#define RS_B 272
#define B_TILE_B (32 * RS_B)
#define STAGE_B (2*A_TILE_B + 2*B_TILE_B)
#define OFF_AHI 0
#define OFF_ALO A_TILE_B
#define OFF_BHI (2*A_TILE_B)
#define OFF_BLO (2*A_TILE_B + B_TILE_B)
#define MM_SMEM_BYTES (2 * STAGE_B)

#define LDM_X4N(r0,r1,r2,r3,addr) LDM_X4(r0,r1,r2,r3,addr)
#define LDM_X2(r0,r1,addr) \
    asm volatile("ldmatrix.sync.aligned.m8n8.x2.shared.b16 {%0,%1}, [%2];" \
        : "=r"(r0),"=r"(r1) : "r"(addr))

template<int MODE>
__global__ void __launch_bounds__(256, 1) mm_kernel(
    const float* __restrict__ Ain, const float* __restrict__ Bin, int ldb,
    const float* __restrict__ bias, float* __restrict__ outp)
{
    extern __shared__ __align__(16) char dsm[];
    const float* __restrict__ Ap = (MODE == 0) ? Ain : g_ctx;

    const int tid = threadIdx.x;
    const int wid = tid >> 5, lane = tid & 31;
    const int bm = blockIdx.y * BM, bn = blockIdx.x * BN;
    const int wm = (wid & 1) * 64, wn = (wid >> 1) * 32;
    const uint32_t sbase = s2u(dsm);

    float acc[4][4][4];
#pragma unroll
    for (int mi = 0; mi < 4; mi++)
#pragma unroll
        for (int ni = 0; ni < 4; ni++)
#pragma unroll
            for (int r = 0; r < 4; r++) acc[mi][ni][r] = 0.f;

    const float* __restrict__ aptr = Ap + (long)(bm + (tid >> 1)) * MMK + (tid & 1) * 16;
    const float* __restrict__ bptr = Bin + (long)(tid >> 3) * ldb + bn + (tid & 7) * 16;

    float4 va0, va1, va2, va3, vb0, vb1, vb2, vb3;
#define LOADC(k0) do { \
    const float* _a = aptr + (k0); \
    va0 = *(const float4*)(_a + 0);  va1 = *(const float4*)(_a + 4); \
    va2 = *(const float4*)(_a + 8);  va3 = *(const float4*)(_a + 12); \
    const float* _b = bptr + (long)(k0) * ldb; \
    vb0 = *(const float4*)(_b + 0);  vb1 = *(const float4*)(_b + 4); \
    vb2 = *(const float4*)(_b + 8);  vb3 = *(const float4*)(_b + 12); \
} while(0)

    LOADC(0);

    const int laneA_row = lane & 15, laneA_half = (lane >> 4) * 16;
    const uint32_t laneB_row = (lane & 7) + ((lane >> 3) & 1) * 8;

    for (int i = 0; i < NCHUNK; i++) {
        const int buf = i & 1;
        char* sp = dsm + buf * STAGE_B;
        {
            char* pa = sp + (tid >> 1) * RS_A + (tid & 1) * 32;
            uint32_t h0,h1,h2,h3,h4,h5,h6,h7, l0,l1,l2,l3,l4,l5,l6,l7;
            CVT_HILO(va0.x, va0.y, h0, l0);  CVT_HILO(va0.z, va0.w, h1, l1);
            CVT_HILO(va1.x, va1.y, h2, l2);  CVT_HILO(va1.z, va1.w, h3, l3);
            CVT_HILO(va2.x, va2.y, h4, l4);  CVT_HILO(va2.z, va2.w, h5, l5);
            CVT_HILO(va3.x, va3.y, h6, l6);  CVT_HILO(va3.z, va3.w, h7, l7);
            *(uint4*)(pa + OFF_AHI +  0) = make_uint4(h0, h1, h2, h3);
            *(uint4*)(pa + OFF_AHI + 16) = make_uint4(h4, h5, h6, h7);
            *(uint4*)(pa + OFF_ALO +  0) = make_uint4(l0, l1, l2, l3);
            *(uint4*)(pa + OFF_ALO + 16) = make_uint4(l4, l5, l6, l7);
        }
        {
            char* pb = sp + (tid >> 3) * RS_B + (tid & 7) * 32;
            uint32_t h0,h1,h2,h3,h4,h5,h6,h7, l0,l1,l2,l3,l4,l5,l6,l7;
            CVT_HILO(vb0.x, vb0.y, h0, l0);  CVT_HILO(vb0.z, vb0.w, h1, l1);
            CVT_HILO(vb1.x, vb1.y, h2, l2);  CVT_HILO(vb1.z, vb1.w, h3, l3);
            CVT_HILO(vb2.x, vb2.y, h4, l4);  CVT_HILO(vb2.z, vb2.w, h5, l5);
            CVT_HILO(vb3.x, vb3.y, h6, l6);  CVT_HILO(vb3.z, vb3.w, h7, l7);
            *(uint4*)(pb + OFF_BHI +  0) = make_uint4(h0, h1, h2, h3);
            *(uint4*)(pb + OFF_BHI + 16) = make_uint4(h4, h5, h6, h7);
            *(uint4*)(pb + OFF_BLO +  0) = make_uint4(l0, l1, l2, l3);
            *(uint4*)(pb + OFF_BLO + 16) = make_uint4(l4, l5, l6, l7);
        }
        __syncthreads();

        if (i + 1 < NCHUNK) LOADC((i + 1) * BKC);

        const uint32_t stb  = sbase + buf * STAGE_B;
        const uint32_t sAhi = stb + OFF_AHI;
        const uint32_t sAlo = stb + OFF_ALO;
        const uint32_t sBhi = stb + OFF_BHI;
        const uint32_t sBlo = stb + OFF_BLO;

#pragma unroll
        for (int kk = 0; kk < 2; kk++) {
            const uint32_t koffA = kk * 32;
            const uint32_t browB = (kk * 16 + laneB_row) * RS_B;
            uint32_t bh0,bh1,bh2,bh3,bh4,bh5,bh6,bh7;
            uint32_t bl0,bl1,bl2,bl3,bl4,bl5,bl6,bl7;
            LDM_X2T(bh0, bh1, sBhi + browB + (wn + 0*8) * 2);
            LDM_X2T(bh2, bh3, sBhi + browB + (wn + 1*8) * 2);
            LDM_X2T(bh4, bh5, sBhi + browB + (wn + 2*8) * 2);
            LDM_X2T(bh6, bh7, sBhi + browB + (wn + 3*8) * 2);
            LDM_X2T(bl0, bl1, sBlo + browB + (wn + 0*8) * 2);
            LDM_X2T(bl2, bl3, sBlo + browB + (wn + 1*8) * 2);
            LDM_X2T(bl4, bl5, sBlo + browB + (wn + 2*8) * 2);
            LDM_X2T(bl6, bl7, sBlo + browB + (wn + 3*8) * 2);
#pragma unroll
            for (int mi = 0; mi < 4; mi++) {
                uint32_t a0, a1, a2, a3;
                uint32_t aa = sAhi + (wm + mi*16 + laneA_row) * RS_A + laneA_half + koffA;
                LDM_X4(a0, a1, a2, a3, aa);
                MMA_BF16(acc[mi][0][0],acc[mi][0][1],acc[mi][0][2],acc[mi][0][3], a0,a1,a2,a3, bh0,bh1);
                MMA_BF16(acc[mi][1][0],acc[mi][1][1],acc[mi][1][2],acc[mi][1][3], a0,a1,a2,a3, bh2,bh3);
                MMA_BF16(acc[mi][2][0],acc[mi][2][1],acc[mi][2][2],acc[mi][2][3], a0,a1,a2,a3, bh4,bh5);
                MMA_BF16(acc[mi][3][0],acc[mi][3][1],acc[mi][3][2],acc[mi][3][3], a0,a1,a2,a3, bh6,bh7);
                MMA_BF16(acc[mi][0][0],acc[mi][0][1],acc[mi][0][2],acc[mi][0][3], a0,a1,a2,a3, bl0,bl1);
                MMA_BF16(acc[mi][1][0],acc[mi][1][1],acc[mi][1][2],acc[mi][1][3], a0,a1,a2,a3, bl2,bl3);
                MMA_BF16(acc[mi][2][0],acc[mi][2][1],acc[mi][2][2],acc[mi][2][3], a0,a1,a2,a3, bl4,bl5);
                MMA_BF16(acc[mi][3][0],acc[mi][3][1],acc[mi][3][2],acc[mi][3][3], a0,a1,a2,a3, bl6,bl7);
            }
#pragma unroll
            for (int mi = 0; mi < 4; mi++) {
                uint32_t a0, a1, a2, a3;
                uint32_t aa = sAlo + (wm + mi*16 + laneA_row) * RS_A + laneA_half + koffA;
                LDM_X4(a0, a1, a2, a3, aa);
                MMA_BF16(acc[mi][0][0],acc[mi][0][1],acc[mi][0][2],acc[mi][0][3], a0,a1,a2,a3, bh0,bh1);
                MMA_BF16(acc[mi][1][0],acc[mi][1][1],acc[mi][1][2],acc[mi][1][3], a0,a1,a2,a3, bh2,bh3);
                MMA_BF16(acc[mi][2][0],acc[mi][2][1],acc[mi][2][2],acc[mi][2][3], a0,a1,a2,a3, bh4,bh5);
                MMA_BF16(acc[mi][3][0],acc[mi][3][1],acc[mi][3][2],acc[mi][3][3], a0,a1,a2,a3, bh6,bh7);
            }
        }
    }
#undef LOADC

    const int lane4 = lane >> 2, lane2 = (lane & 3) * 2;
#pragma unroll
    for (int mi = 0; mi < 4; mi++) {
        int r0 = bm + wm + mi*16 + lane4;
        int r1 = r0 + 8;
#pragma unroll
        for (int ni = 0; ni < 4; ni++) {
            int ng = bn + wn + ni*8 + lane2;
            float bz0 = bias[ng], bz1 = bias[ng + 1];
            float c0 = acc[mi][ni][0] + bz0, c1 = acc[mi][ni][1] + bz1;
            float c2 = acc[mi][ni][2] + bz0, c3 = acc[mi][ni][3] + bz1;
            if (MODE == 1) {
                float2 v0 = {c0, c1}, v1 = {c2, c3};
                *(float2*)&outp[(long)r0 * NC + ng] = v0;
                *(float2*)&outp[(long)r1 * NC + ng] = v1;
            } else {
                const int sel = bn >> 10;
                int n = ng & (NC - 1);
                int head = n >> 6, dh = n & (DHD - 1);
                int b0 = r0 >> 11, t0 = r0 & (NT - 1);
                int b1 = r1 >> 11, t1 = r1 & (NT - 1);
                if (sel == 0) { c0 *= 0.125f; c1 *= 0.125f; c2 *= 0.125f; c3 *= 0.125f; }
                uint32_t hi0, lo0, hi1, lo1;
                CVT_HILO(c0, c1, hi0, lo0);
                CVT_HILO(c2, c3, hi1, lo1);
                __nv_bfloat16* dhi = (sel == 0) ? g_qhi : (sel == 1) ? g_khi : g_vhi;
                __nv_bfloat16* dlo = (sel == 0) ? g_qlo : (sel == 1) ? g_klo : g_vlo;
                long e0 = ((long)(((b0 << 4) + head) * NT + t0)) * DHD + dh;
                long e1 = ((long)(((b1 << 4) + head) * NT + t1)) * DHD + dh;
                *(uint32_t*)(dhi + e0) = hi0;  *(uint32_t*)(dlo + e0) = lo0;
                *(uint32_t*)(dhi + e1) = hi1;  *(uint32_t*)(dlo + e1) = lo1;
            }
        }
    }
}

// ---------------- tensor-core flash attention, BQ=256, X4 ldmatrix --------------
#define RS_F 144
#define QTILE_B (256 * RS_F)              // 36864
#define KVT_B   (64 * RS_F)               // 9216
#define STAGE_F (4 * KVT_B)               // 36864
#define OFF_Q    0
#define OFF_ST   (2 * QTILE_B)            // 73728
#define OFF_BAND (OFF_ST + 2 * STAGE_F)   // 147456
#define FL_SMEM  (OFF_BAND + 2 * 336 * 8) // 152832

__global__ void __launch_bounds__(256, 1) flash_kernel()
{
    extern __shared__ __align__(16) char fsm[];
    const int tid = threadIdx.x, wid = tid >> 5, lane = tid & 31;
    const int bh = blockIdx.y, h = bh & (NH - 1), b = bh >> 4;
    const int q0 = blockIdx.x * 256;
    const uint32_t sb = s2u(fsm);
    const long kvbase = (long)bh * NT * DHD;
    const int hb = h * NDIST;
    float2* bandp = (float2*)(fsm + OFF_BAND);

    // ---- load Q tile (256 rows hi + lo) ----
#pragma unroll
    for (int j = 0; j < 2; j++) {
        int rowid = tid + j * 256;
        int a = rowid >> 8, row = rowid & 255;
        const uint4* src = (const uint4*)((a ? g_qlo : g_qhi) + kvbase + (long)(q0 + row) * DHD);
        uint4* dst = (uint4*)(fsm + OFF_Q + a * QTILE_B + row * RS_F);
#pragma unroll
        for (int u = 0; u < 8; u++) dst[u] = src[u];
    }

#define CP_STAGE(tile, buf) do { \
    int a_ = tid >> 6; int row_ = tid & 63; \
    const __nv_bfloat16* g_ = (a_ == 0) ? g_khi : (a_ == 1) ? g_klo : (a_ == 2) ? g_vhi : g_vlo; \
    const char* src_ = (const char*)(g_ + kvbase + (long)((tile) * 64 + row_) * DHD); \
    uint32_t dst_ = sb + OFF_ST + (buf) * STAGE_F + a_ * KVT_B + row_ * RS_F; \
    CP_ASYNC16(dst_ +   0, src_ +   0); CP_ASYNC16(dst_ +  16, src_ +  16); \
    CP_ASYNC16(dst_ +  32, src_ +  32); CP_ASYNC16(dst_ +  48, src_ +  48); \
    CP_ASYNC16(dst_ +  64, src_ +  64); CP_ASYNC16(dst_ +  80, src_ +  80); \
    CP_ASYNC16(dst_ +  96, src_ +  96); CP_ASYNC16(dst_ + 112, src_ + 112); \
} while(0)

#define BAND_W(tile, buf) do { \
    int base_ = q0 - (tile) * 64 + 1984; \
    for (int j_ = tid; j_ < 319; j_ += 256) { \
        int d0_ = base_ + j_; int d1_ = d0_ - 1; if (d1_ < 0) d1_ = 0; \
        bandp[(buf) * 336 + j_] = make_float2(g_bias[hb + d0_], g_bias[hb + d1_]); \
    } \
} while(0)

    CP_STAGE(0, 0);
    CP_COMMIT();
    BAND_W(0, 0);

    float o[2][8][4];
#pragma unroll
    for (int mf = 0; mf < 2; mf++)
#pragma unroll
        for (int nt = 0; nt < 8; nt++)
#pragma unroll
            for (int r = 0; r < 4; r++) o[mf][nt][r] = 0.f;
    float mst[2][2], lst[2][2];
#pragma unroll
    for (int mf = 0; mf < 2; mf++) { mst[mf][0] = mst[mf][1] = -1e30f; lst[mf][0] = lst[mf][1] = 0.f; }

    const int g = lane >> 2, t2 = (lane & 3) * 2;
    const int krow_lane = ((lane >> 4) & 1) * 8 + (lane & 7);
    const int kbyte     = ((lane >> 3) & 1) * 16;
    const int vrow_lane = ((lane >> 3) & 1) * 8 + (lane & 7);
    const int vcol      = (lane >> 4);
    const int qrow_lane = lane & 15;
    const int qbyte     = (lane >> 4) * 16;

    for (int i = 0; i < 32; i++) {
        const int buf = i & 1;
        CP_WAIT0();
        __syncthreads();
        if (i + 1 < 32) {
            CP_STAGE(i + 1, buf ^ 1);
            CP_COMMIT();
            BAND_W(i + 1, buf ^ 1);
        }

        const uint32_t stg  = sb + OFF_ST + buf * STAGE_F;
        const uint32_t sKhi = stg;
        const uint32_t sVhi = stg + 2 * KVT_B;

        // ---- S = (Q/8) K^T (3-term split) ----
        float s[2][8][4];
#pragma unroll
        for (int mf = 0; mf < 2; mf++)
#pragma unroll
            for (int nt = 0; nt < 8; nt++)
#pragma unroll
                for (int r = 0; r < 4; r++) s[mf][nt][r] = 0.f;

#pragma unroll
        for (int kt = 0; kt < 4; kt++) {
            uint32_t qh[2][4], ql[2][4];
#pragma unroll
            for (int mf = 0; mf < 2; mf++) {
                uint32_t qa = sb + OFF_Q + (wid*32 + mf*16 + qrow_lane) * RS_F + qbyte + kt * 32;
                LDM_X4(qh[mf][0], qh[mf][1], qh[mf][2], qh[mf][3], qa);
                LDM_X4(ql[mf][0], ql[mf][1], ql[mf][2], ql[mf][3], qa + QTILE_B);
            }
#pragma unroll
            for (int p = 0; p < 4; p++) {
                uint32_t k0,k1,k2,k3, m0,m1,m2,m3;
                uint32_t ka = sKhi + (p*16 + krow_lane) * RS_F + kbyte + kt * 32;
                LDM_X4(k0, k1, k2, k3, ka);
                LDM_X4(m0, m1, m2, m3, ka + KVT_B);
#pragma unroll
                for (int mf = 0; mf < 2; mf++) {
                    MMA_BF16(s[mf][2*p][0],s[mf][2*p][1],s[mf][2*p][2],s[mf][2*p][3],
                             qh[mf][0],qh[mf][1],qh[mf][2],qh[mf][3], k0,k1);
                    MMA_BF16(s[mf][2*p][0],s[mf][2*p][1],s[mf][2*p][2],s[mf][2*p][3],
                             qh[mf][0],qh[mf][1],qh[mf][2],qh[mf][3], m0,m1);
                    MMA_BF16(s[mf][2*p][0],s[mf][2*p][1],s[mf][2*p][2],s[mf][2*p][3],
                             ql[mf][0],ql[mf][1],ql[mf][2],ql[mf][3], k0,k1);
                    MMA_BF16(s[mf][2*p+1][0],s[mf][2*p+1][1],s[mf][2*p+1][2],s[mf][2*p+1][3],
                             qh[mf][0],qh[mf][1],qh[mf][2],qh[mf][3], k2,k3);
                    MMA_BF16(s[mf][2*p+1][0],s[mf][2*p+1][1],s[mf][2*p+1][2],s[mf][2*p+1][3],
                             qh[mf][0],qh[mf][1],qh[mf][2],qh[mf][3], m2,m3);
                    MMA_BF16(s[mf][2*p+1][0],s[mf][2*p+1][1],s[mf][2*p+1][2],s[mf][2*p+1][3],
                             ql[mf][0],ql[mf][1],ql[mf][2],ql[mf][3], k2,k3);
                }
            }
        }

        // ---- bias + online softmax (registers) ----
        const float2* bd = bandp + buf * 336;
#pragma unroll
        for (int mf = 0; mf < 2; mf++) {
            const int e0 = wid*32 + mf*16 + g + 63 - t2;
            float mx0 = -1e30f, mx1 = -1e30f;
#pragma unroll
            for (int nt = 0; nt < 8; nt++) {
                float2 b0v = bd[e0 - 8*nt];
                float2 b1v = bd[e0 + 8 - 8*nt];
                s[mf][nt][0] += b0v.x;  s[mf][nt][1] += b0v.y;
                s[mf][nt][2] += b1v.x;  s[mf][nt][3] += b1v.y;
                mx0 = fmaxf(mx0, fmaxf(s[mf][nt][0], s[mf][nt][1]));
                mx1 = fmaxf(mx1, fmaxf(s[mf][nt][2], s[mf][nt][3]));
            }
            mx0 = fmaxf(mx0, __shfl_xor_sync(0xffffffffu, mx0, 1));
            mx0 = fmaxf(mx0, __shfl_xor_sync(0xffffffffu, mx0, 2));
            mx1 = fmaxf(mx1, __shfl_xor_sync(0xffffffffu, mx1, 1));
            mx1 = fmaxf(mx1, __shfl_xor_sync(0xffffffffu, mx1, 2));
            float mn0 = fmaxf(mst[mf][0], mx0), mn1 = fmaxf(mst[mf][1], mx1);
            float sc0 = fast_exp(mst[mf][0] - mn0), sc1 = fast_exp(mst[mf][1] - mn1);
            float su0 = 0.f, su1 = 0.f;
#pragma unroll
            for (int nt = 0; nt < 8; nt++) {
                s[mf][nt][0] = fast_exp(s[mf][nt][0] - mn0);
                s[mf][nt][1] = fast_exp(s[mf][nt][1] - mn0);
                s[mf][nt][2] = fast_exp(s[mf][nt][2] - mn1);
                s[mf][nt][3] = fast_exp(s[mf][nt][3] - mn1);
                su0 += s[mf][nt][0] + s[mf][nt][1];
                su1 += s[mf][nt][2] + s[mf][nt][3];
            }
            su0 += __shfl_xor_sync(0xffffffffu, su0, 1);
            su0 += __shfl_xor_sync(0xffffffffu, su0, 2);
            su1 += __shfl_xor_sync(0xffffffffu, su1, 1);
            su1 += __shfl_xor_sync(0xffffffffu, su1, 2);
            lst[mf][0] = lst[mf][0] * sc0 + su0;  mst[mf][0] = mn0;
            lst[mf][1] = lst[mf][1] * sc1 + su1;  mst[mf][1] = mn1;
#pragma unroll
            for (int nt = 0; nt < 8; nt++) {
                o[mf][nt][0] *= sc0; o[mf][nt][1] *= sc0;
                o[mf][nt][2] *= sc1; o[mf][nt][3] *= sc1;
            }
        }

        // ---- O += P V  (P repacked in registers, 3-term split) ----
#pragma unroll
        for (int st = 0; st < 4; st++) {
            uint32_t ph[2][4], pl[2][4];
#pragma unroll
            for (int mf = 0; mf < 2; mf++) {
                CVT_HILO(s[mf][2*st][0],   s[mf][2*st][1],   ph[mf][0], pl[mf][0]);
                CVT_HILO(s[mf][2*st][2],   s[mf][2*st][3],   ph[mf][1], pl[mf][1]);
                CVT_HILO(s[mf][2*st+1][0], s[mf][2*st+1][1], ph[mf][2], pl[mf][2]);
                CVT_HILO(s[mf][2*st+1][2], s[mf][2*st+1][3], ph[mf][3], pl[mf][3]);
            }
#pragma unroll
            for (int p2 = 0; p2 < 4; p2++) {
                uint32_t v0,v1,v2,v3, w0,w1,w2,w3;
                uint32_t va = sVhi + (st*16 + vrow_lane) * RS_F + (p2*2 + vcol) * 16;
                LDM_X4T(v0, v1, v2, v3, va);
                LDM_X4T(w0, w1, w2, w3, va + KVT_B);
#pragma unroll
                for (int mf = 0; mf < 2; mf++) {
                    MMA_BF16(o[mf][2*p2][0],o[mf][2*p2][1],o[mf][2*p2][2],o[mf][2*p2][3],
                             ph[mf][0],ph[mf][1],ph[mf][2],ph[mf][3], v0,v1);
                    MMA_BF16(o[mf][2*p2][0],o[mf][2*p2][1],o[mf][2*p2][2],o[mf][2*p2][3],
                             ph[mf][0],ph[mf][1],ph[mf][2],ph[mf][3], w0,w1);
                    MMA_BF16(o[mf][2*p2][0],o[mf][2*p2][1],o[mf][2*p2][2],o[mf][2*p2][3],
                             pl[mf][0],pl[mf][1],pl[mf][2],pl[mf][3], v0,v1);
                    MMA_BF16(o[mf][2*p2+1][0],o[mf][2*p2+1][1],o[mf][2*p2+1][2],o[mf][2*p2+1][3],
                             ph[mf][0],ph[mf][1],ph[mf][2],ph[mf][3], v2,v3);
                    MMA_BF16(o[mf][2*p2+1][0],o[mf][2*p2+1][1],o[mf][2*p2+1][2],o[mf][2*p2+1][3],
                             ph[mf][0],ph[mf][1],ph[mf][2],ph[mf][3], w2,w3);
                    MMA_BF16(o[mf][2*p2+1][0],o[mf][2*p2+1][1],o[mf][2*p2+1][2],o[mf][2*p2+1][3],
                             pl[mf][0],pl[mf][1],pl[mf][2],pl[mf][3], v2,v3);
                }
            }
        }
    }

    // ---- normalize + write ctx ----
#pragma unroll
    for (int mf = 0; mf < 2; mf++) {
        float inv0 = 1.f / lst[mf][0], inv1 = 1.f / lst[mf][1];
        int t0 = q0 + wid*32 + mf*16 + g, t1 = t0 + 8;
        float* c0p = g_ctx + (long)(b * NT + t0) * NC + h * DHD + t2;
        float* c1p = g_ctx + (long)(b * NT + t1) * NC + h * DHD + t2;
#pragma unroll
        for (int nt = 0; nt < 8; nt++) {
            float2 u0 = {o[mf][nt][0] * inv0, o[mf][nt][1] * inv0};
            float2 u1 = {o[mf][nt][2] * inv1, o[mf][nt][3] * inv1};
            *(float2*)(c0p + nt * 8) = u0;
            *(float2*)(c1p + nt * 8) = u1;
        }
    }
#undef CP_STAGE
#undef BAND_W
}

// ---------------- launch ---------------------------------------------------------
extern "C" void kernel_launch(void* const* d_in, const int* in_sizes, int n_in,
                              void* d_out, int out_size)
{
    const float* x     = (const float*)d_in[0];
    const float* w_qkv = (const float*)d_in[1];
    const float* b_qkv = (const float*)d_in[2];
    const float* w_out = (const float*)d_in[3];
    const float* b_out = (const float*)d_in[4];
    const float* w1    = (const float*)d_in[5];
    const float* b1    = (const float*)d_in[6];
    const float* w2    = (const float*)d_in[7];
    const float* b2    = (const float*)d_in[8];
    float* out = (float*)d_out;

    cudaFuncSetAttribute(flash_kernel, cudaFuncAttributeMaxDynamicSharedMemorySize,
                         FL_SMEM);
    cudaFuncSetAttribute(mm_kernel<0>, cudaFuncAttributeMaxDynamicSharedMemorySize,
                         MM_SMEM_BYTES);
    cudaFuncSetAttribute(mm_kernel<1>, cudaFuncAttributeMaxDynamicSharedMemorySize,
                         MM_SMEM_BYTES);

    rpe_kernel<<<(NDIST + 255) / 256, 256>>>(w1, b1, w2, b2);

    {   // QKV projection
        dim3 gq(N3C / BN, NM / BM);
        mm_kernel<0><<<gq, 256, MM_SMEM_BYTES>>>(x, w_qkv, N3C, b_qkv, nullptr);
    }
    {   // flash attention (tensor cores, BQ=256)
        dim3 gf(NT / 256, NB * NH);
        flash_kernel<<<gf, 256, FL_SMEM>>>();
    }
    {   // output projection
        dim3 go(NC / BN, NM / BM);
        mm_kernel<1><<<go, 256, MM_SMEM_BYTES>>>(nullptr, w_out, NC, b_out, out);
    }
}

// round 10
// speedup vs baseline: 2.8226x; 1.0546x over previous
#include <cuda_runtime.h>
#include <cuda_bf16.h>
#include <math.h>
#include <stdint.h>

#define NB 2
#define NT 2048
#define NC 1024
#define NH 16
#define DHD 64
#define NHID 32
#define N3C 3072
#define NM 4096
#define NDIST 4095
#define MMK 1024
#define BM 128
#define BN 128
#define BKC 32
#define NCHUNK (MMK/BKC)
#define LOG2E 1.4426950408889634f

// ---------------- statics: same 67.2MB footprint as passing R6-R8 ----------------
__device__ __align__(16) __nv_bfloat16 g_qhi[NB*NH*NT*DHD];  // [bh][t][dh], pre-scaled log2e/8
__device__ __align__(16) __nv_bfloat16 g_qlo[NB*NH*NT*DHD];
__device__ __align__(16) __nv_bfloat16 g_khi[NB*NH*NT*DHD];
__device__ __align__(16) __nv_bfloat16 g_klo[NB*NH*NT*DHD];
__device__ __align__(16) __nv_bfloat16 g_vhi[NB*NH*NT*DHD];
__device__ __align__(16) __nv_bfloat16 g_vlo[NB*NH*NT*DHD];
__device__ __align__(16) float g_ctx[NM*NC];
__device__ float g_bias[NH*NDIST];          // pre-scaled by log2e

// ================= PTX helpers ==================================================
__device__ __forceinline__ uint32_t s2u(const void* p) {
    uint32_t a;
    asm("{ .reg .u64 t; cvta.to.shared.u64 t, %1; cvt.u32.u64 %0, t; }" : "=r"(a) : "l"(p));
    return a;
}
#define CP_ASYNC16(dst, src) \
    asm volatile("cp.async.cg.shared.global [%0], [%1], 16;" :: "r"(dst), "l"(src))
#define CP_COMMIT() asm volatile("cp.async.commit_group;" ::: "memory")
#define CP_WAIT0()  asm volatile("cp.async.wait_group 0;" ::: "memory")

#define LDM_X4(r0,r1,r2,r3,addr) \
    asm volatile("ldmatrix.sync.aligned.m8n8.x4.shared.b16 {%0,%1,%2,%3}, [%4];" \
        : "=r"(r0),"=r"(r1),"=r"(r2),"=r"(r3) : "r"(addr))
#define LDM_X4T(r0,r1,r2,r3,addr) \
    asm volatile("ldmatrix.sync.aligned.m8n8.x4.trans.shared.b16 {%0,%1,%2,%3}, [%4];" \
        : "=r"(r0),"=r"(r1),"=r"(r2),"=r"(r3) : "r"(addr))
#define LDM_X2T(r0,r1,addr) \
    asm volatile("ldmatrix.sync.aligned.m8n8.x2.trans.shared.b16 {%0,%1}, [%2];" \
        : "=r"(r0),"=r"(r1) : "r"(addr))
#define LDM_X2(r0,r1,addr) \
    asm volatile("ldmatrix.sync.aligned.m8n8.x2.shared.b16 {%0,%1}, [%2];" \
        : "=r"(r0),"=r"(r1) : "r"(addr))

#define MMA_BF16(c0,c1,c2,c3,a0,a1,a2,a3,b0,b1) \
    asm volatile("mma.sync.aligned.m16n8k16.row.col.f32.bf16.bf16.f32 " \
                 "{%0,%1,%2,%3}, {%4,%5,%6,%7}, {%8,%9}, {%0,%1,%2,%3};" \
                 : "+f"(c0), "+f"(c1), "+f"(c2), "+f"(c3) \
                 : "r"(a0), "r"(a1), "r"(a2), "r"(a3), "r"(b0), "r"(b1))

#define CVT_HILO(x, y, hi, lo) do{ \
    asm("cvt.rn.bf16x2.f32 %0, %1, %2;" : "=r"(hi) : "f"(y), "f"(x)); \
    float _lx = (x) - __uint_as_float((hi) << 16); \
    float _ly = (y) - __uint_as_float((hi) & 0xFFFF0000u); \
    asm("cvt.rn.bf16x2.f32 %0, %1, %2;" : "=r"(lo) : "f"(_ly), "f"(_lx)); \
}while(0)

// MUFU exp2 (values already in log2 domain)
#define EX2(d, s) asm("ex2.approx.ftz.f32 %0, %1;" : "=f"(d) : "f"(s))

// ---------------- RPE bias table (pre-scaled by log2e) --------------------------
__global__ void rpe_kernel(const float* __restrict__ w1, const float* __restrict__ b1,
                           const float* __restrict__ w2, const float* __restrict__ b2)
{
    int d = blockIdx.x * blockDim.x + threadIdx.x;
    if (d >= NDIST) return;
    float rel = (float)(d - (NT - 1));
    float sgn = (rel > 0.f) ? 1.f : ((rel < 0.f) ? -1.f : 0.f);
    float x = sgn * log1pf(fabsf(rel));
    float h[NHID];
#pragma unroll
    for (int j = 0; j < NHID; j++)
        h[j] = fmaxf(fmaf(x, __ldg(&w1[j]), __ldg(&b1[j])), 0.f);
#pragma unroll
    for (int hd = 0; hd < NH; hd++) {
        float acc = __ldg(&b2[hd]);
#pragma unroll
        for (int j = 0; j < NHID; j++)
            acc = fmaf(h[j], __ldg(&w2[j*NH + hd]), acc);
        g_bias[hd*NDIST + d] = acc * LOG2E;
    }
}

// ---------------- mma.sync bf16 3-term split GEMM (structure = R8) --------------
#define RS_A 80
#define A_TILE_B (128 * RS_A)
#define RS_B 272
#define B_TILE_B (32 * RS_B)
#define STAGE_B (2*A_TILE_B + 2*B_TILE_B)
#define OFF_AHI 0
#define OFF_ALO A_TILE_B
#define OFF_BHI (2*A_TILE_B)
#define OFF_BLO (2*A_TILE_B + B_TILE_B)
#define MM_SMEM_BYTES (2 * STAGE_B)

template<int MODE>
__global__ void __launch_bounds__(256, 1) mm_kernel(
    const float* __restrict__ Ain, const float* __restrict__ Bin, int ldb,
    const float* __restrict__ bias, float* __restrict__ outp)
{
    extern __shared__ __align__(16) char dsm[];
    const float* __restrict__ Ap = (MODE == 0) ? Ain : g_ctx;

    const int tid = threadIdx.x;
    const int wid = tid >> 5, lane = tid & 31;
    const int bm = blockIdx.y * BM, bn = blockIdx.x * BN;
    const int wm = (wid & 1) * 64, wn = (wid >> 1) * 32;
    const uint32_t sbase = s2u(dsm);

    float acc[4][4][4];
#pragma unroll
    for (int mi = 0; mi < 4; mi++)
#pragma unroll
        for (int ni = 0; ni < 4; ni++)
#pragma unroll
            for (int r = 0; r < 4; r++) acc[mi][ni][r] = 0.f;

    const float* __restrict__ aptr = Ap + (long)(bm + (tid >> 1)) * MMK + (tid & 1) * 16;
    const float* __restrict__ bptr = Bin + (long)(tid >> 3) * ldb + bn + (tid & 7) * 16;

    float4 va0, va1, va2, va3, vb0, vb1, vb2, vb3;
#define LOADC(k0) do { \
    const float* _a = aptr + (k0); \
    va0 = *(const float4*)(_a + 0);  va1 = *(const float4*)(_a + 4); \
    va2 = *(const float4*)(_a + 8);  va3 = *(const float4*)(_a + 12); \
    const float* _b = bptr + (long)(k0) * ldb; \
    vb0 = *(const float4*)(_b + 0);  vb1 = *(const float4*)(_b + 4); \
    vb2 = *(const float4*)(_b + 8);  vb3 = *(const float4*)(_b + 12); \
} while(0)

    LOADC(0);

    const int laneA_row = lane & 15, laneA_half = (lane >> 4) * 16;
    const uint32_t laneB_row = (lane & 7) + ((lane >> 3) & 1) * 8;

    for (int i = 0; i < NCHUNK; i++) {
        const int buf = i & 1;
        char* sp = dsm + buf * STAGE_B;
        {
            char* pa = sp + (tid >> 1) * RS_A + (tid & 1) * 32;
            uint32_t h0,h1,h2,h3,h4,h5,h6,h7, l0,l1,l2,l3,l4,l5,l6,l7;
            CVT_HILO(va0.x, va0.y, h0, l0);  CVT_HILO(va0.z, va0.w, h1, l1);
            CVT_HILO(va1.x, va1.y, h2, l2);  CVT_HILO(va1.z, va1.w, h3, l3);
            CVT_HILO(va2.x, va2.y, h4, l4);  CVT_HILO(va2.z, va2.w, h5, l5);
            CVT_HILO(va3.x, va3.y, h6, l6);  CVT_HILO(va3.z, va3.w, h7, l7);
            *(uint4*)(pa + OFF_AHI +  0) = make_uint4(h0, h1, h2, h3);
            *(uint4*)(pa + OFF_AHI + 16) = make_uint4(h4, h5, h6, h7);
            *(uint4*)(pa + OFF_ALO +  0) = make_uint4(l0, l1, l2, l3);
            *(uint4*)(pa + OFF_ALO + 16) = make_uint4(l4, l5, l6, l7);
        }
        {
            char* pb = sp + (tid >> 3) * RS_B + (tid & 7) * 32;
            uint32_t h0,h1,h2,h3,h4,h5,h6,h7, l0,l1,l2,l3,l4,l5,l6,l7;
            CVT_HILO(vb0.x, vb0.y, h0, l0);  CVT_HILO(vb0.z, vb0.w, h1, l1);
            CVT_HILO(vb1.x, vb1.y, h2, l2);  CVT_HILO(vb1.z, vb1.w, h3, l3);
            CVT_HILO(vb2.x, vb2.y, h4, l4);  CVT_HILO(vb2.z, vb2.w, h5, l5);
            CVT_HILO(vb3.x, vb3.y, h6, l6);  CVT_HILO(vb3.z, vb3.w, h7, l7);
            *(uint4*)(pb + OFF_BHI +  0) = make_uint4(h0, h1, h2, h3);
            *(uint4*)(pb + OFF_BHI + 16) = make_uint4(h4, h5, h6, h7);
            *(uint4*)(pb + OFF_BLO +  0) = make_uint4(l0, l1, l2, l3);
            *(uint4*)(pb + OFF_BLO + 16) = make_uint4(l4, l5, l6, l7);
        }
        __syncthreads();

        if (i + 1 < NCHUNK) LOADC((i + 1) * BKC);

        const uint32_t stb  = sbase + buf * STAGE_B;
        const uint32_t sAhi = stb + OFF_AHI;
        const uint32_t sAlo = stb + OFF_ALO;
        const uint32_t sBhi = stb + OFF_BHI;
        const uint32_t sBlo = stb + OFF_BLO;

#pragma unroll
        for (int kk = 0; kk < 2; kk++) {
            const uint32_t koffA = kk * 32;
            const uint32_t browB = (kk * 16 + laneB_row) * RS_B;
            uint32_t bh0,bh1,bh2,bh3,bh4,bh5,bh6,bh7;
            uint32_t bl0,bl1,bl2,bl3,bl4,bl5,bl6,bl7;
            LDM_X2T(bh0, bh1, sBhi + browB + (wn + 0*8) * 2);
            LDM_X2T(bh2, bh3, sBhi + browB + (wn + 1*8) * 2);
            LDM_X2T(bh4, bh5, sBhi + browB + (wn + 2*8) * 2);
            LDM_X2T(bh6, bh7, sBhi + browB + (wn + 3*8) * 2);
            LDM_X2T(bl0, bl1, sBlo + browB + (wn + 0*8) * 2);
            LDM_X2T(bl2, bl3, sBlo + browB + (wn + 1*8) * 2);
            LDM_X2T(bl4, bl5, sBlo + browB + (wn + 2*8) * 2);
            LDM_X2T(bl6, bl7, sBlo + browB + (wn + 3*8) * 2);
#pragma unroll
            for (int mi = 0; mi < 4; mi++) {
                uint32_t a0, a1, a2, a3;
                uint32_t aa = sAhi + (wm + mi*16 + laneA_row) * RS_A + laneA_half + koffA;
                LDM_X4(a0, a1, a2, a3, aa);
                MMA_BF16(acc[mi][0][0],acc[mi][0][1],acc[mi][0][2],acc[mi][0][3], a0,a1,a2,a3, bh0,bh1);
                MMA_BF16(acc[mi][1][0],acc[mi][1][1],acc[mi][1][2],acc[mi][1][3], a0,a1,a2,a3, bh2,bh3);
                MMA_BF16(acc[mi][2][0],acc[mi][2][1],acc[mi][2][2],acc[mi][2][3], a0,a1,a2,a3, bh4,bh5);
                MMA_BF16(acc[mi][3][0],acc[mi][3][1],acc[mi][3][2],acc[mi][3][3], a0,a1,a2,a3, bh6,bh7);
                MMA_BF16(acc[mi][0][0],acc[mi][0][1],acc[mi][0][2],acc[mi][0][3], a0,a1,a2,a3, bl0,bl1);
                MMA_BF16(acc[mi][1][0],acc[mi][1][1],acc[mi][1][2],acc[mi][1][3], a0,a1,a2,a3, bl2,bl3);
                MMA_BF16(acc[mi][2][0],acc[mi][2][1],acc[mi][2][2],acc[mi][2][3], a0,a1,a2,a3, bl4,bl5);
                MMA_BF16(acc[mi][3][0],acc[mi][3][1],acc[mi][3][2],acc[mi][3][3], a0,a1,a2,a3, bl6,bl7);
            }
#pragma unroll
            for (int mi = 0; mi < 4; mi++) {
                uint32_t a0, a1, a2, a3;
                uint32_t aa = sAlo + (wm + mi*16 + laneA_row) * RS_A + laneA_half + koffA;
                LDM_X4(a0, a1, a2, a3, aa);
                MMA_BF16(acc[mi][0][0],acc[mi][0][1],acc[mi][0][2],acc[mi][0][3], a0,a1,a2,a3, bh0,bh1);
                MMA_BF16(acc[mi][1][0],acc[mi][1][1],acc[mi][1][2],acc[mi][1][3], a0,a1,a2,a3, bh2,bh3);
                MMA_BF16(acc[mi][2][0],acc[mi][2][1],acc[mi][2][2],acc[mi][2][3], a0,a1,a2,a3, bh4,bh5);
                MMA_BF16(acc[mi][3][0],acc[mi][3][1],acc[mi][3][2],acc[mi][3][3], a0,a1,a2,a3, bh6,bh7);
            }
        }
    }
#undef LOADC

    const int lane4 = lane >> 2, lane2 = (lane & 3) * 2;
#pragma unroll
    for (int mi = 0; mi < 4; mi++) {
        int r0 = bm + wm + mi*16 + lane4;
        int r1 = r0 + 8;
#pragma unroll
        for (int ni = 0; ni < 4; ni++) {
            int ng = bn + wn + ni*8 + lane2;
            float bz0 = bias[ng], bz1 = bias[ng + 1];
            float c0 = acc[mi][ni][0] + bz0, c1 = acc[mi][ni][1] + bz1;
            float c2 = acc[mi][ni][2] + bz0, c3 = acc[mi][ni][3] + bz1;
            if (MODE == 1) {
                float2 v0 = {c0, c1}, v1 = {c2, c3};
                *(float2*)&outp[(long)r0 * NC + ng] = v0;
                *(float2*)&outp[(long)r1 * NC + ng] = v1;
            } else {
                const int sel = bn >> 10;
                int n = ng & (NC - 1);
                int head = n >> 6, dh = n & (DHD - 1);
                int b0 = r0 >> 11, t0 = r0 & (NT - 1);
                int b1 = r1 >> 11, t1 = r1 & (NT - 1);
                if (sel == 0) {   // fold softmax 1/8 scale AND log2e into Q
                    const float qs = 0.125f * LOG2E;
                    c0 *= qs; c1 *= qs; c2 *= qs; c3 *= qs;
                }
                uint32_t hi0, lo0, hi1, lo1;
                CVT_HILO(c0, c1, hi0, lo0);
                CVT_HILO(c2, c3, hi1, lo1);
                __nv_bfloat16* dhi = (sel == 0) ? g_qhi : (sel == 1) ? g_khi : g_vhi;
                __nv_bfloat16* dlo = (sel == 0) ? g_qlo : (sel == 1) ? g_klo : g_vlo;
                long e0 = ((long)(((b0 << 4) + head) * NT + t0)) * DHD + dh;
                long e1 = ((long)(((b1 << 4) + head) * NT + t1)) * DHD + dh;
                *(uint32_t*)(dhi + e0) = hi0;  *(uint32_t*)(dlo + e0) = lo0;
                *(uint32_t*)(dhi + e1) = hi1;  *(uint32_t*)(dlo + e1) = lo1;
            }
        }
    }
}

// ---------------- tensor-core flash attention, BQ=256, MUFU softmax -------------
#define RS_F 144
#define QTILE_B (256 * RS_F)
#define KVT_B   (64 * RS_F)
#define STAGE_F (4 * KVT_B)
#define OFF_Q    0
#define OFF_ST   (2 * QTILE_B)
#define OFF_BAND (OFF_ST + 2 * STAGE_F)
#define FL_SMEM  (OFF_BAND + 2 * 336 * 8)

__global__ void __launch_bounds__(256, 1) flash_kernel()
{
    extern __shared__ __align__(16) char fsm[];
    const int tid = threadIdx.x, wid = tid >> 5, lane = tid & 31;
    const int bh = blockIdx.y, h = bh & (NH - 1), b = bh >> 4;
    const int q0 = blockIdx.x * 256;
    const uint32_t sb = s2u(fsm);
    const long kvbase = (long)bh * NT * DHD;
    const int hb = h * NDIST;
    float2* bandp = (float2*)(fsm + OFF_BAND);

    // ---- load Q tile (256 rows hi + lo) ----
#pragma unroll
    for (int j = 0; j < 2; j++) {
        int rowid = tid + j * 256;
        int a = rowid >> 8, row = rowid & 255;
        const uint4* src = (const uint4*)((a ? g_qlo : g_qhi) + kvbase + (long)(q0 + row) * DHD);
        uint4* dst = (uint4*)(fsm + OFF_Q + a * QTILE_B + row * RS_F);
#pragma unroll
        for (int u = 0; u < 8; u++) dst[u] = src[u];
    }

#define CP_STAGE(tile, buf) do { \
    int a_ = tid >> 6; int row_ = tid & 63; \
    const __nv_bfloat16* g_ = (a_ == 0) ? g_khi : (a_ == 1) ? g_klo : (a_ == 2) ? g_vhi : g_vlo; \
    const char* src_ = (const char*)(g_ + kvbase + (long)((tile) * 64 + row_) * DHD); \
    uint32_t dst_ = sb + OFF_ST + (buf) * STAGE_F + a_ * KVT_B + row_ * RS_F; \
    CP_ASYNC16(dst_ +   0, src_ +   0); CP_ASYNC16(dst_ +  16, src_ +  16); \
    CP_ASYNC16(dst_ +  32, src_ +  32); CP_ASYNC16(dst_ +  48, src_ +  48); \
    CP_ASYNC16(dst_ +  64, src_ +  64); CP_ASYNC16(dst_ +  80, src_ +  80); \
    CP_ASYNC16(dst_ +  96, src_ +  96); CP_ASYNC16(dst_ + 112, src_ + 112); \
} while(0)

#define BAND_W(tile, buf) do { \
    int base_ = q0 - (tile) * 64 + 1984; \
    for (int j_ = tid; j_ < 319; j_ += 256) { \
        int d0_ = base_ + j_; int d1_ = d0_ - 1; if (d1_ < 0) d1_ = 0; \
        bandp[(buf) * 336 + j_] = make_float2(g_bias[hb + d0_], g_bias[hb + d1_]); \
    } \
} while(0)

    CP_STAGE(0, 0);
    CP_COMMIT();
    BAND_W(0, 0);

    float o[2][8][4];
#pragma unroll
    for (int mf = 0; mf < 2; mf++)
#pragma unroll
        for (int nt = 0; nt < 8; nt++)
#pragma unroll
            for (int r = 0; r < 4; r++) o[mf][nt][r] = 0.f;
    float mst[2][2], lst[2][2];
#pragma unroll
    for (int mf = 0; mf < 2; mf++) { mst[mf][0] = mst[mf][1] = -1e30f; lst[mf][0] = lst[mf][1] = 0.f; }

    const int g = lane >> 2, t2 = (lane & 3) * 2;
    const int krow_lane = ((lane >> 4) & 1) * 8 + (lane & 7);
    const int kbyte     = ((lane >> 3) & 1) * 16;
    const int vrow_lane = ((lane >> 3) & 1) * 8 + (lane & 7);
    const int vcol      = (lane >> 4);
    const int qrow_lane = lane & 15;
    const int qbyte     = (lane >> 4) * 16;

    for (int i = 0; i < 32; i++) {
        const int buf = i & 1;
        CP_WAIT0();
        __syncthreads();
        if (i + 1 < 32) {
            CP_STAGE(i + 1, buf ^ 1);
            CP_COMMIT();
            BAND_W(i + 1, buf ^ 1);
        }

        const uint32_t stg  = sb + OFF_ST + buf * STAGE_F;
        const uint32_t sKhi = stg;
        const uint32_t sVhi = stg + 2 * KVT_B;

        // ---- S = Q K^T, log2 domain (3-term split) ----
        float s[2][8][4];
#pragma unroll
        for (int mf = 0; mf < 2; mf++)
#pragma unroll
            for (int nt = 0; nt < 8; nt++)
#pragma unroll
                for (int r = 0; r < 4; r++) s[mf][nt][r] = 0.f;

#pragma unroll
        for (int kt = 0; kt < 4; kt++) {
            uint32_t qh[2][4], ql[2][4];
#pragma unroll
            for (int mf = 0; mf < 2; mf++) {
                uint32_t qa = sb + OFF_Q + (wid*32 + mf*16 + qrow_lane) * RS_F + qbyte + kt * 32;
                LDM_X4(qh[mf][0], qh[mf][1], qh[mf][2], qh[mf][3], qa);
                LDM_X4(ql[mf][0], ql[mf][1], ql[mf][2], ql[mf][3], qa + QTILE_B);
            }
#pragma unroll
            for (int p = 0; p < 4; p++) {
                uint32_t k0,k1,k2,k3, m0,m1,m2,m3;
                uint32_t ka = sKhi + (p*16 + krow_lane) * RS_F + kbyte + kt * 32;
                LDM_X4(k0, k1, k2, k3, ka);
                LDM_X4(m0, m1, m2, m3, ka + KVT_B);
#pragma unroll
                for (int mf = 0; mf < 2; mf++) {
                    MMA_BF16(s[mf][2*p][0],s[mf][2*p][1],s[mf][2*p][2],s[mf][2*p][3],
                             qh[mf][0],qh[mf][1],qh[mf][2],qh[mf][3], k0,k1);
                    MMA_BF16(s[mf][2*p][0],s[mf][2*p][1],s[mf][2*p][2],s[mf][2*p][3],
                             qh[mf][0],qh[mf][1],qh[mf][2],qh[mf][3], m0,m1);
                    MMA_BF16(s[mf][2*p][0],s[mf][2*p][1],s[mf][2*p][2],s[mf][2*p][3],
                             ql[mf][0],ql[mf][1],ql[mf][2],ql[mf][3], k0,k1);
                    MMA_BF16(s[mf][2*p+1][0],s[mf][2*p+1][1],s[mf][2*p+1][2],s[mf][2*p+1][3],
                             qh[mf][0],qh[mf][1],qh[mf][2],qh[mf][3], k2,k3);
                    MMA_BF16(s[mf][2*p+1][0],s[mf][2*p+1][1],s[mf][2*p+1][2],s[mf][2*p+1][3],
                             qh[mf][0],qh[mf][1],qh[mf][2],qh[mf][3], m2,m3);
                    MMA_BF16(s[mf][2*p+1][0],s[mf][2*p+1][1],s[mf][2*p+1][2],s[mf][2*p+1][3],
                             ql[mf][0],ql[mf][1],ql[mf][2],ql[mf][3], k2,k3);
                }
            }
        }

        // ---- bias + online softmax: exp -> MUFU ex2 (log2 domain) ----
        const float2* bd = bandp + buf * 336;
#pragma unroll
        for (int mf = 0; mf < 2; mf++) {
            const int e0 = wid*32 + mf*16 + g + 63 - t2;
            float mx0 = -1e30f, mx1 = -1e30f;
#pragma unroll
            for (int nt = 0; nt < 8; nt++) {
                float2 b0v = bd[e0 - 8*nt];
                float2 b1v = bd[e0 + 8 - 8*nt];
                s[mf][nt][0] += b0v.x;  s[mf][nt][1] += b0v.y;
                s[mf][nt][2] += b1v.x;  s[mf][nt][3] += b1v.y;
                mx0 = fmaxf(mx0, fmaxf(s[mf][nt][0], s[mf][nt][1]));
                mx1 = fmaxf(mx1, fmaxf(s[mf][nt][2], s[mf][nt][3]));
            }
            mx0 = fmaxf(mx0, __shfl_xor_sync(0xffffffffu, mx0, 1));
            mx0 = fmaxf(mx0, __shfl_xor_sync(0xffffffffu, mx0, 2));
            mx1 = fmaxf(mx1, __shfl_xor_sync(0xffffffffu, mx1, 1));
            mx1 = fmaxf(mx1, __shfl_xor_sync(0xffffffffu, mx1, 2));
            float mn0 = fmaxf(mst[mf][0], mx0), mn1 = fmaxf(mst[mf][1], mx1);
            float a0 = mst[mf][0] - mn0, a1 = mst[mf][1] - mn1;
            float sc0, sc1;
            EX2(sc0, a0);
            EX2(sc1, a1);
            float su0 = 0.f, su1 = 0.f;
#pragma unroll
            for (int nt = 0; nt < 8; nt++) {
                float d0 = s[mf][nt][0] - mn0, d1 = s[mf][nt][1] - mn0;
                float d2 = s[mf][nt][2] - mn1, d3 = s[mf][nt][3] - mn1;
                EX2(s[mf][nt][0], d0);
                EX2(s[mf][nt][1], d1);
                EX2(s[mf][nt][2], d2);
                EX2(s[mf][nt][3], d3);
                su0 += s[mf][nt][0] + s[mf][nt][1];
                su1 += s[mf][nt][2] + s[mf][nt][3];
            }
            su0 += __shfl_xor_sync(0xffffffffu, su0, 1);
            su0 += __shfl_xor_sync(0xffffffffu, su0, 2);
            su1 += __shfl_xor_sync(0xffffffffu, su1, 1);
            su1 += __shfl_xor_sync(0xffffffffu, su1, 2);
            lst[mf][0] = lst[mf][0] * sc0 + su0;  mst[mf][0] = mn0;
            lst[mf][1] = lst[mf][1] * sc1 + su1;  mst[mf][1] = mn1;
#pragma unroll
            for (int nt = 0; nt < 8; nt++) {
                o[mf][nt][0] *= sc0; o[mf][nt][1] *= sc0;
                o[mf][nt][2] *= sc1; o[mf][nt][3] *= sc1;
            }
        }

        // ---- O += P V  (P repacked in registers, 3-term split) ----
#pragma unroll
        for (int st = 0; st < 4; st++) {
            uint32_t ph[2][4], pl[2][4];
#pragma unroll
            for (int mf = 0; mf < 2; mf++) {
                CVT_HILO(s[mf][2*st][0],   s[mf][2*st][1],   ph[mf][0], pl[mf][0]);
                CVT_HILO(s[mf][2*st][2],   s[mf][2*st][3],   ph[mf][1], pl[mf][1]);
                CVT_HILO(s[mf][2*st+1][0], s[mf][2*st+1][1], ph[mf][2], pl[mf][2]);
                CVT_HILO(s[mf][2*st+1][2], s[mf][2*st+1][3], ph[mf][3], pl[mf][3]);
            }
#pragma unroll
            for (int p2 = 0; p2 < 4; p2++) {
                uint32_t v0,v1,v2,v3, w0,w1,w2,w3;
                uint32_t va = sVhi + (st*16 + vrow_lane) * RS_F + (p2*2 + vcol) * 16;
                LDM_X4T(v0, v1, v2, v3, va);
                LDM_X4T(w0, w1, w2, w3, va + KVT_B);
#pragma unroll
                for (int mf = 0; mf < 2; mf++) {
                    MMA_BF16(o[mf][2*p2][0],o[mf][2*p2][1],o[mf][2*p2][2],o[mf][2*p2][3],
                             ph[mf][0],ph[mf][1],ph[mf][2],ph[mf][3], v0,v1);
                    MMA_BF16(o[mf][2*p2][0],o[mf][2*p2][1],o[mf][2*p2][2],o[mf][2*p2][3],
                             ph[mf][0],ph[mf][1],ph[mf][2],ph[mf][3], w0,w1);
                    MMA_BF16(o[mf][2*p2][0],o[mf][2*p2][1],o[mf][2*p2][2],o[mf][2*p2][3],
                             pl[mf][0],pl[mf][1],pl[mf][2],pl[mf][3], v0,v1);
                    MMA_BF16(o[mf][2*p2+1][0],o[mf][2*p2+1][1],o[mf][2*p2+1][2],o[mf][2*p2+1][3],
                             ph[mf][0],ph[mf][1],ph[mf][2],ph[mf][3], v2,v3);
                    MMA_BF16(o[mf][2*p2+1][0],o[mf][2*p2+1][1],o[mf][2*p2+1][2],o[mf][2*p2+1][3],
                             ph[mf][0],ph[mf][1],ph[mf][2],ph[mf][3], w2,w3);
                    MMA_BF16(o[mf][2*p2+1][0],o[mf][2*p2+1][1],o[mf][2*p2+1][2],o[mf][2*p2+1][3],
                             pl[mf][0],pl[mf][1],pl[mf][2],pl[mf][3], v2,v3);
                }
            }
        }
    }

    // ---- normalize + write ctx ----
#pragma unroll
    for (int mf = 0; mf < 2; mf++) {
        float inv0 = 1.f / lst[mf][0], inv1 = 1.f / lst[mf][1];
        int t0 = q0 + wid*32 + mf*16 + g, t1 = t0 + 8;
        float* c0p = g_ctx + (long)(b * NT + t0) * NC + h * DHD + t2;
        float* c1p = g_ctx + (long)(b * NT + t1) * NC + h * DHD + t2;
#pragma unroll
        for (int nt = 0; nt < 8; nt++) {
            float2 u0 = {o[mf][nt][0] * inv0, o[mf][nt][1] * inv0};
            float2 u1 = {o[mf][nt][2] * inv1, o[mf][nt][3] * inv1};
            *(float2*)(c0p + nt * 8) = u0;
            *(float2*)(c1p + nt * 8) = u1;
        }
    }
#undef CP_STAGE
#undef BAND_W
}

// ---------------- launch ---------------------------------------------------------
extern "C" void kernel_launch(void* const* d_in, const int* in_sizes, int n_in,
                              void* d_out, int out_size)
{
    const float* x     = (const float*)d_in[0];
    const float* w_qkv = (const float*)d_in[1];
    const float* b_qkv = (const float*)d_in[2];
    const float* w_out = (const float*)d_in[3];
    const float* b_out = (const float*)d_in[4];
    const float* w1    = (const float*)d_in[5];
    const float* b1    = (const float*)d_in[6];
    const float* w2    = (const float*)d_in[7];
    const float* b2    = (const float*)d_in[8];
    float* out = (float*)d_out;

    cudaFuncSetAttribute(flash_kernel, cudaFuncAttributeMaxDynamicSharedMemorySize,
                         FL_SMEM);
    cudaFuncSetAttribute(mm_kernel<0>, cudaFuncAttributeMaxDynamicSharedMemorySize,
                         MM_SMEM_BYTES);
    cudaFuncSetAttribute(mm_kernel<1>, cudaFuncAttributeMaxDynamicSharedMemorySize,
                         MM_SMEM_BYTES);

    rpe_kernel<<<(NDIST + 255) / 256, 256>>>(w1, b1, w2, b2);

    {   // QKV projection
        dim3 gq(N3C / BN, NM / BM);
        mm_kernel<0><<<gq, 256, MM_SMEM_BYTES>>>(x, w_qkv, N3C, b_qkv, nullptr);
    }
    {   // flash attention (tensor cores, MUFU softmax)
        dim3 gf(NT / 256, NB * NH);
        flash_kernel<<<gf, 256, FL_SMEM>>>();
    }
    {   // output projection
        dim3 go(NC / BN, NM / BM);
        mm_kernel<1><<<go, 256, MM_SMEM_BYTES>>>(nullptr, w_out, NC, b_out, out);
    }
}

// round 11
// speedup vs baseline: 2.8694x; 1.0166x over previous
#include <cuda_runtime.h>
#include <cuda_bf16.h>
#include <math.h>
#include <stdint.h>

#define NB 2
#define NT 2048
#define NC 1024
#define NH 16
#define DHD 64
#define NHID 32
#define N3C 3072
#define NM 4096
#define NDIST 4095
#define MMK 1024
#define BM 128
#define BN 128
#define BKC 32
#define NCHUNK (MMK/BKC)
#define LOG2E 1.4426950408889634f

// ---------------- statics: same 67.2MB footprint as passing R6-R10 ---------------
__device__ __align__(16) __nv_bfloat16 g_qhi[NB*NH*NT*DHD];  // [bh][t][dh], pre-scaled log2e/8
__device__ __align__(16) __nv_bfloat16 g_qlo[NB*NH*NT*DHD];
__device__ __align__(16) __nv_bfloat16 g_khi[NB*NH*NT*DHD];
__device__ __align__(16) __nv_bfloat16 g_klo[NB*NH*NT*DHD];
__device__ __align__(16) __nv_bfloat16 g_vhi[NB*NH*NT*DHD];
__device__ __align__(16) __nv_bfloat16 g_vlo[NB*NH*NT*DHD];
// g_ctx doubles as: (a) xhi/xlo bf16 scratch for mm<0> (before flash),
//                   (b) fp32 attention output (written by flash, read by mm<1>).
__device__ __align__(16) float g_ctx[NM*NC];
__device__ float g_bias[NH*NDIST];          // pre-scaled by log2e

// ================= PTX helpers ==================================================
__device__ __forceinline__ uint32_t s2u(const void* p) {
    uint32_t a;
    asm("{ .reg .u64 t; cvta.to.shared.u64 t, %1; cvt.u32.u64 %0, t; }" : "=r"(a) : "l"(p));
    return a;
}
#define CP_ASYNC16(dst, src) \
    asm volatile("cp.async.cg.shared.global [%0], [%1], 16;" :: "r"(dst), "l"(src))
#define CP_COMMIT() asm volatile("cp.async.commit_group;" ::: "memory")
#define CP_WAIT1()  asm volatile("cp.async.wait_group 1;" ::: "memory")
#define CP_WAIT0()  asm volatile("cp.async.wait_group 0;" ::: "memory")

#define LDM_X4(r0,r1,r2,r3,addr) \
    asm volatile("ldmatrix.sync.aligned.m8n8.x4.shared.b16 {%0,%1,%2,%3}, [%4];" \
        : "=r"(r0),"=r"(r1),"=r"(r2),"=r"(r3) : "r"(addr))
#define LDM_X4T(r0,r1,r2,r3,addr) \
    asm volatile("ldmatrix.sync.aligned.m8n8.x4.trans.shared.b16 {%0,%1,%2,%3}, [%4];" \
        : "=r"(r0),"=r"(r1),"=r"(r2),"=r"(r3) : "r"(addr))
#define LDM_X2T(r0,r1,addr) \
    asm volatile("ldmatrix.sync.aligned.m8n8.x2.trans.shared.b16 {%0,%1}, [%2];" \
        : "=r"(r0),"=r"(r1) : "r"(addr))

#define MMA_BF16(c0,c1,c2,c3,a0,a1,a2,a3,b0,b1) \
    asm volatile("mma.sync.aligned.m16n8k16.row.col.f32.bf16.bf16.f32 " \
                 "{%0,%1,%2,%3}, {%4,%5,%6,%7}, {%8,%9}, {%0,%1,%2,%3};" \
                 : "+f"(c0), "+f"(c1), "+f"(c2), "+f"(c3) \
                 : "r"(a0), "r"(a1), "r"(a2), "r"(a3), "r"(b0), "r"(b1))

#define CVT_HILO(x, y, hi, lo) do{ \
    asm("cvt.rn.bf16x2.f32 %0, %1, %2;" : "=r"(hi) : "f"(y), "f"(x)); \
    float _lx = (x) - __uint_as_float((hi) << 16); \
    float _ly = (y) - __uint_as_float((hi) & 0xFFFF0000u); \
    asm("cvt.rn.bf16x2.f32 %0, %1, %2;" : "=r"(lo) : "f"(_ly), "f"(_lx)); \
}while(0)

#define EX2(d, s) asm("ex2.approx.ftz.f32 %0, %1;" : "=f"(d) : "f"(s))

// ---------------- RPE bias table (pre-scaled by log2e) --------------------------
__global__ void rpe_kernel(const float* __restrict__ w1, const float* __restrict__ b1,
                           const float* __restrict__ w2, const float* __restrict__ b2)
{
    int d = blockIdx.x * blockDim.x + threadIdx.x;
    if (d >= NDIST) return;
    float rel = (float)(d - (NT - 1));
    float sgn = (rel > 0.f) ? 1.f : ((rel < 0.f) ? -1.f : 0.f);
    float x = sgn * log1pf(fabsf(rel));
    float h[NHID];
#pragma unroll
    for (int j = 0; j < NHID; j++)
        h[j] = fmaxf(fmaf(x, __ldg(&w1[j]), __ldg(&b1[j])), 0.f);
#pragma unroll
    for (int hd = 0; hd < NH; hd++) {
        float acc = __ldg(&b2[hd]);
#pragma unroll
        for (int j = 0; j < NHID; j++)
            acc = fmaf(h[j], __ldg(&w2[j*NH + hd]), acc);
        g_bias[hd*NDIST + d] = acc * LOG2E;
    }
}

// ---------------- x -> bf16 hi/lo (into g_ctx scratch) ---------------------------
__global__ void conv_x_kernel(const float* __restrict__ x) {
    __nv_bfloat16* xhi = (__nv_bfloat16*)g_ctx;
    __nv_bfloat16* xlo = xhi + (long)NM * NC;
    long i = (long)(blockIdx.x * blockDim.x + threadIdx.x) * 4;
    float4 v = *(const float4*)&x[i];
    uint32_t h01, l01, h23, l23;
    CVT_HILO(v.x, v.y, h01, l01);
    CVT_HILO(v.z, v.w, h23, l23);
    *(uint2*)&xhi[i] = make_uint2(h01, h23);
    *(uint2*)&xlo[i] = make_uint2(l01, l23);
}

// ---------------- mma.sync bf16 3-term split GEMM --------------------------------
// MODE 0: A = pre-converted x (bf16 hi/lo in g_ctx scratch, cp.async direct);
//         B = w_qkv fp32 (convert in-kernel); epilogue scatters q/k/v bf16 hi/lo.
// MODE 1: A = g_ctx fp32 (convert in-kernel); B = w_out fp32; plain store.
#define RS_A 80
#define A_TILE_B (128 * RS_A)
#define RS_B 272
#define B_TILE_B (32 * RS_B)
#define STAGE_B (2*A_TILE_B + 2*B_TILE_B)
#define OFF_AHI 0
#define OFF_ALO A_TILE_B
#define OFF_BHI (2*A_TILE_B)
#define OFF_BLO (2*A_TILE_B + B_TILE_B)
#define MM_SMEM_BYTES (2 * STAGE_B)

template<int MODE>
__global__ void __launch_bounds__(256, 1) mm_kernel(
    const float* __restrict__ Ain, const float* __restrict__ Bin, int ldb,
    const float* __restrict__ bias, float* __restrict__ outp)
{
    extern __shared__ __align__(16) char dsm[];
    const float* __restrict__ Ap = (MODE == 0) ? Ain : g_ctx;
    const __nv_bfloat16* __restrict__ Axhi = (const __nv_bfloat16*)g_ctx;
    const __nv_bfloat16* __restrict__ Axlo = Axhi + (long)NM * NC;

    const int tid = threadIdx.x;
    const int wid = tid >> 5, lane = tid & 31;
    const int bm = blockIdx.y * BM, bn = blockIdx.x * BN;
    const int wm = (wid & 1) * 64, wn = (wid >> 1) * 32;
    const uint32_t sbase = s2u(dsm);

    float acc[4][4][4];
#pragma unroll
    for (int mi = 0; mi < 4; mi++)
#pragma unroll
        for (int ni = 0; ni < 4; ni++)
#pragma unroll
            for (int r = 0; r < 4; r++) acc[mi][ni][r] = 0.f;

    const float* __restrict__ aptr = Ap + (long)(bm + (tid >> 1)) * MMK + (tid & 1) * 16;
    const float* __restrict__ bptr = Bin + (long)(tid >> 3) * ldb + bn + (tid & 7) * 16;
    const int ar = tid >> 1, ah = tid & 1;   // MODE 0 A cp.async geometry

#define CP_A(chunk, stage) do { \
    long off_ = (long)(bm + ar) * MMK + (chunk) * BKC + ah * 16; \
    uint32_t d_ = sbase + (stage) * STAGE_B + ar * RS_A + ah * 32; \
    CP_ASYNC16(d_ + OFF_AHI,      Axhi + off_); \
    CP_ASYNC16(d_ + OFF_AHI + 16, Axhi + off_ + 8); \
    CP_ASYNC16(d_ + OFF_ALO,      Axlo + off_); \
    CP_ASYNC16(d_ + OFF_ALO + 16, Axlo + off_ + 8); \
    CP_COMMIT(); \
} while(0)

    float4 va0, va1, va2, va3, vb0, vb1, vb2, vb3;
#define LOADC(k0) do { \
    if (MODE == 1) { \
        const float* _a = aptr + (k0); \
        va0 = *(const float4*)(_a + 0);  va1 = *(const float4*)(_a + 4); \
        va2 = *(const float4*)(_a + 8);  va3 = *(const float4*)(_a + 12); \
    } \
    const float* _b = bptr + (long)(k0) * ldb; \
    vb0 = *(const float4*)(_b + 0);  vb1 = *(const float4*)(_b + 4); \
    vb2 = *(const float4*)(_b + 8);  vb3 = *(const float4*)(_b + 12); \
} while(0)

    if (MODE == 0) CP_A(0, 0);
    LOADC(0);

    const int laneA_row = lane & 15, laneA_half = (lane >> 4) * 16;
    const uint32_t laneB_row = (lane & 7) + ((lane >> 3) & 1) * 8;

    for (int i = 0; i < NCHUNK; i++) {
        const int buf = i & 1;
        char* sp = dsm + buf * STAGE_B;
        if (MODE == 1) {
            char* pa = sp + (tid >> 1) * RS_A + (tid & 1) * 32;
            uint32_t h0,h1,h2,h3,h4,h5,h6,h7, l0,l1,l2,l3,l4,l5,l6,l7;
            CVT_HILO(va0.x, va0.y, h0, l0);  CVT_HILO(va0.z, va0.w, h1, l1);
            CVT_HILO(va1.x, va1.y, h2, l2);  CVT_HILO(va1.z, va1.w, h3, l3);
            CVT_HILO(va2.x, va2.y, h4, l4);  CVT_HILO(va2.z, va2.w, h5, l5);
            CVT_HILO(va3.x, va3.y, h6, l6);  CVT_HILO(va3.z, va3.w, h7, l7);
            *(uint4*)(pa + OFF_AHI +  0) = make_uint4(h0, h1, h2, h3);
            *(uint4*)(pa + OFF_AHI + 16) = make_uint4(h4, h5, h6, h7);
            *(uint4*)(pa + OFF_ALO +  0) = make_uint4(l0, l1, l2, l3);
            *(uint4*)(pa + OFF_ALO + 16) = make_uint4(l4, l5, l6, l7);
        }
        {
            char* pb = sp + (tid >> 3) * RS_B + (tid & 7) * 32;
            uint32_t h0,h1,h2,h3,h4,h5,h6,h7, l0,l1,l2,l3,l4,l5,l6,l7;
            CVT_HILO(vb0.x, vb0.y, h0, l0);  CVT_HILO(vb0.z, vb0.w, h1, l1);
            CVT_HILO(vb1.x, vb1.y, h2, l2);  CVT_HILO(vb1.z, vb1.w, h3, l3);
            CVT_HILO(vb2.x, vb2.y, h4, l4);  CVT_HILO(vb2.z, vb2.w, h5, l5);
            CVT_HILO(vb3.x, vb3.y, h6, l6);  CVT_HILO(vb3.z, vb3.w, h7, l7);
            *(uint4*)(pb + OFF_BHI +  0) = make_uint4(h0, h1, h2, h3);
            *(uint4*)(pb + OFF_BHI + 16) = make_uint4(h4, h5, h6, h7);
            *(uint4*)(pb + OFF_BLO +  0) = make_uint4(l0, l1, l2, l3);
            *(uint4*)(pb + OFF_BLO + 16) = make_uint4(l4, l5, l6, l7);
        }
        if (MODE == 0) {
            if (i + 1 < NCHUNK) { CP_A(i + 1, buf ^ 1); CP_WAIT1(); }
            else                { CP_WAIT0(); }
        }
        __syncthreads();

        if (i + 1 < NCHUNK) LOADC((i + 1) * BKC);

        const uint32_t stb  = sbase + buf * STAGE_B;
        const uint32_t sAhi = stb + OFF_AHI;
        const uint32_t sAlo = stb + OFF_ALO;
        const uint32_t sBhi = stb + OFF_BHI;
        const uint32_t sBlo = stb + OFF_BLO;

#pragma unroll
        for (int kk = 0; kk < 2; kk++) {
            const uint32_t koffA = kk * 32;
            const uint32_t browB = (kk * 16 + laneB_row) * RS_B;
            uint32_t bh0,bh1,bh2,bh3,bh4,bh5,bh6,bh7;
            uint32_t bl0,bl1,bl2,bl3,bl4,bl5,bl6,bl7;
            LDM_X2T(bh0, bh1, sBhi + browB + (wn + 0*8) * 2);
            LDM_X2T(bh2, bh3, sBhi + browB + (wn + 1*8) * 2);
            LDM_X2T(bh4, bh5, sBhi + browB + (wn + 2*8) * 2);
            LDM_X2T(bh6, bh7, sBhi + browB + (wn + 3*8) * 2);
            LDM_X2T(bl0, bl1, sBlo + browB + (wn + 0*8) * 2);
            LDM_X2T(bl2, bl3, sBlo + browB + (wn + 1*8) * 2);
            LDM_X2T(bl4, bl5, sBlo + browB + (wn + 2*8) * 2);
            LDM_X2T(bl6, bl7, sBlo + browB + (wn + 3*8) * 2);
#pragma unroll
            for (int mi = 0; mi < 4; mi++) {
                uint32_t a0, a1, a2, a3;
                uint32_t aa = sAhi + (wm + mi*16 + laneA_row) * RS_A + laneA_half + koffA;
                LDM_X4(a0, a1, a2, a3, aa);
                MMA_BF16(acc[mi][0][0],acc[mi][0][1],acc[mi][0][2],acc[mi][0][3], a0,a1,a2,a3, bh0,bh1);
                MMA_BF16(acc[mi][1][0],acc[mi][1][1],acc[mi][1][2],acc[mi][1][3], a0,a1,a2,a3, bh2,bh3);
                MMA_BF16(acc[mi][2][0],acc[mi][2][1],acc[mi][2][2],acc[mi][2][3], a0,a1,a2,a3, bh4,bh5);
                MMA_BF16(acc[mi][3][0],acc[mi][3][1],acc[mi][3][2],acc[mi][3][3], a0,a1,a2,a3, bh6,bh7);
                MMA_BF16(acc[mi][0][0],acc[mi][0][1],acc[mi][0][2],acc[mi][0][3], a0,a1,a2,a3, bl0,bl1);
                MMA_BF16(acc[mi][1][0],acc[mi][1][1],acc[mi][1][2],acc[mi][1][3], a0,a1,a2,a3, bl2,bl3);
                MMA_BF16(acc[mi][2][0],acc[mi][2][1],acc[mi][2][2],acc[mi][2][3], a0,a1,a2,a3, bl4,bl5);
                MMA_BF16(acc[mi][3][0],acc[mi][3][1],acc[mi][3][2],acc[mi][3][3], a0,a1,a2,a3, bl6,bl7);
            }
#pragma unroll
            for (int mi = 0; mi < 4; mi++) {
                uint32_t a0, a1, a2, a3;
                uint32_t aa = sAlo + (wm + mi*16 + laneA_row) * RS_A + laneA_half + koffA;
                LDM_X4(a0, a1, a2, a3, aa);
                MMA_BF16(acc[mi][0][0],acc[mi][0][1],acc[mi][0][2],acc[mi][0][3], a0,a1,a2,a3, bh0,bh1);
                MMA_BF16(acc[mi][1][0],acc[mi][1][1],acc[mi][1][2],acc[mi][1][3], a0,a1,a2,a3, bh2,bh3);
                MMA_BF16(acc[mi][2][0],acc[mi][2][1],acc[mi][2][2],acc[mi][2][3], a0,a1,a2,a3, bh4,bh5);
                MMA_BF16(acc[mi][3][0],acc[mi][3][1],acc[mi][3][2],acc[mi][3][3], a0,a1,a2,a3, bh6,bh7);
            }
        }
    }
#undef LOADC
#undef CP_A

    const int lane4 = lane >> 2, lane2 = (lane & 3) * 2;
#pragma unroll
    for (int mi = 0; mi < 4; mi++) {
        int r0 = bm + wm + mi*16 + lane4;
        int r1 = r0 + 8;
#pragma unroll
        for (int ni = 0; ni < 4; ni++) {
            int ng = bn + wn + ni*8 + lane2;
            float bz0 = bias[ng], bz1 = bias[ng + 1];
            float c0 = acc[mi][ni][0] + bz0, c1 = acc[mi][ni][1] + bz1;
            float c2 = acc[mi][ni][2] + bz0, c3 = acc[mi][ni][3] + bz1;
            if (MODE == 1) {
                float2 v0 = {c0, c1}, v1 = {c2, c3};
                *(float2*)&outp[(long)r0 * NC + ng] = v0;
                *(float2*)&outp[(long)r1 * NC + ng] = v1;
            } else {
                const int sel = bn >> 10;
                int n = ng & (NC - 1);
                int head = n >> 6, dh = n & (DHD - 1);
                int b0 = r0 >> 11, t0 = r0 & (NT - 1);
                int b1 = r1 >> 11, t1 = r1 & (NT - 1);
                if (sel == 0) {
                    const float qs = 0.125f * LOG2E;
                    c0 *= qs; c1 *= qs; c2 *= qs; c3 *= qs;
                }
                uint32_t hi0, lo0, hi1, lo1;
                CVT_HILO(c0, c1, hi0, lo0);
                CVT_HILO(c2, c3, hi1, lo1);
                __nv_bfloat16* dhi = (sel == 0) ? g_qhi : (sel == 1) ? g_khi : g_vhi;
                __nv_bfloat16* dlo = (sel == 0) ? g_qlo : (sel == 1) ? g_klo : g_vlo;
                long e0 = ((long)(((b0 << 4) + head) * NT + t0)) * DHD + dh;
                long e1 = ((long)(((b1 << 4) + head) * NT + t1)) * DHD + dh;
                *(uint32_t*)(dhi + e0) = hi0;  *(uint32_t*)(dlo + e0) = lo0;
                *(uint32_t*)(dhi + e1) = hi1;  *(uint32_t*)(dlo + e1) = lo1;
            }
        }
    }
}

// ---------------- tensor-core flash attention, BQ=256, 16 warps -----------------
#define RS_F 144
#define QTILE_B (256 * RS_F)
#define KVT_B   (64 * RS_F)
#define STAGE_F (4 * KVT_B)
#define OFF_Q    0
#define OFF_ST   (2 * QTILE_B)
#define OFF_BAND (OFF_ST + 2 * STAGE_F)
#define FL_SMEM  (OFF_BAND + 2 * 336 * 8)

__global__ void __launch_bounds__(512, 1) flash_kernel()
{
    extern __shared__ __align__(16) char fsm[];
    const int tid = threadIdx.x, wid = tid >> 5, lane = tid & 31;
    const int bh = blockIdx.y, h = bh & (NH - 1), b = bh >> 4;
    const int q0 = blockIdx.x * 256;
    const uint32_t sb = s2u(fsm);
    const long kvbase = (long)bh * NT * DHD;
    const int hb = h * NDIST;
    float2* bandp = (float2*)(fsm + OFF_BAND);

    // ---- load Q tile (512 threads, one 128B row each: 256 rows x {hi,lo}) ----
    {
        int a = tid >> 8, row = tid & 255;
        const uint4* src = (const uint4*)((a ? g_qlo : g_qhi) + kvbase + (long)(q0 + row) * DHD);
        uint4* dst = (uint4*)(fsm + OFF_Q + a * QTILE_B + row * RS_F);
#pragma unroll
        for (int u = 0; u < 8; u++) dst[u] = src[u];
    }

#define CP_STAGE(tile, buf) do { \
    int a_ = tid >> 7; int r2_ = tid & 127; int row_ = r2_ >> 1; \
    const __nv_bfloat16* g_ = (a_ == 0) ? g_khi : (a_ == 1) ? g_klo : (a_ == 2) ? g_vhi : g_vlo; \
    const char* src_ = (const char*)(g_ + kvbase + (long)((tile) * 64 + row_) * DHD) + (r2_ & 1) * 64; \
    uint32_t dst_ = sb + OFF_ST + (buf) * STAGE_F + a_ * KVT_B + row_ * RS_F + (r2_ & 1) * 64; \
    CP_ASYNC16(dst_ +  0, src_ +  0); CP_ASYNC16(dst_ + 16, src_ + 16); \
    CP_ASYNC16(dst_ + 32, src_ + 32); CP_ASYNC16(dst_ + 48, src_ + 48); \
} while(0)

#define BAND_W(tile, buf) do { \
    int base_ = q0 - (tile) * 64 + 1984; \
    if (tid < 319) { \
        int d0_ = base_ + tid; int d1_ = d0_ - 1; if (d1_ < 0) d1_ = 0; \
        bandp[(buf) * 336 + tid] = make_float2(g_bias[hb + d0_], g_bias[hb + d1_]); \
    } \
} while(0)

    CP_STAGE(0, 0);
    CP_COMMIT();
    BAND_W(0, 0);

    float o[8][4];
#pragma unroll
    for (int nt = 0; nt < 8; nt++)
#pragma unroll
        for (int r = 0; r < 4; r++) o[nt][r] = 0.f;
    float rm0 = -1e30f, rm1 = -1e30f, rl0 = 0.f, rl1 = 0.f;

    const int g = lane >> 2, t2 = (lane & 3) * 2;
    const int krow_lane = ((lane >> 4) & 1) * 8 + (lane & 7);
    const int kbyte     = ((lane >> 3) & 1) * 16;
    const int vrow_lane = ((lane >> 3) & 1) * 8 + (lane & 7);
    const int vcol      = (lane >> 4);
    const int qrow_lane = lane & 15;
    const int qbyte     = (lane >> 4) * 16;
    const int e0 = wid * 16 + g + 63 - t2;

    for (int i = 0; i < 32; i++) {
        const int buf = i & 1;
        CP_WAIT0();
        __syncthreads();
        if (i + 1 < 32) {
            CP_STAGE(i + 1, buf ^ 1);
            CP_COMMIT();
            BAND_W(i + 1, buf ^ 1);
        }

        const uint32_t stg  = sb + OFF_ST + buf * STAGE_F;
        const uint32_t sKhi = stg;
        const uint32_t sVhi = stg + 2 * KVT_B;

        // ---- S = Q K^T, log2 domain (3-term split) ----
        float s[8][4];
#pragma unroll
        for (int nt = 0; nt < 8; nt++)
#pragma unroll
            for (int r = 0; r < 4; r++) s[nt][r] = 0.f;

#pragma unroll
        for (int kt = 0; kt < 4; kt++) {
            uint32_t qh0, qh1, qh2, qh3, ql0, ql1, ql2, ql3;
            uint32_t qa = sb + OFF_Q + (wid*16 + qrow_lane) * RS_F + qbyte + kt * 32;
            LDM_X4(qh0, qh1, qh2, qh3, qa);
            LDM_X4(ql0, ql1, ql2, ql3, qa + QTILE_B);
#pragma unroll
            for (int p = 0; p < 4; p++) {
                uint32_t k0,k1,k2,k3, n0,n1,n2,n3;
                uint32_t ka = sKhi + (p*16 + krow_lane) * RS_F + kbyte + kt * 32;
                LDM_X4(k0, k1, k2, k3, ka);
                LDM_X4(n0, n1, n2, n3, ka + KVT_B);
                MMA_BF16(s[2*p][0],s[2*p][1],s[2*p][2],s[2*p][3],
                         qh0,qh1,qh2,qh3, k0,k1);
                MMA_BF16(s[2*p][0],s[2*p][1],s[2*p][2],s[2*p][3],
                         qh0,qh1,qh2,qh3, n0,n1);
                MMA_BF16(s[2*p][0],s[2*p][1],s[2*p][2],s[2*p][3],
                         ql0,ql1,ql2,ql3, k0,k1);
                MMA_BF16(s[2*p+1][0],s[2*p+1][1],s[2*p+1][2],s[2*p+1][3],
                         qh0,qh1,qh2,qh3, k2,k3);
                MMA_BF16(s[2*p+1][0],s[2*p+1][1],s[2*p+1][2],s[2*p+1][3],
                         qh0,qh1,qh2,qh3, n2,n3);
                MMA_BF16(s[2*p+1][0],s[2*p+1][1],s[2*p+1][2],s[2*p+1][3],
                         ql0,ql1,ql2,ql3, k2,k3);
            }
        }

        // ---- bias + online softmax (MUFU ex2, log2 domain) ----
        const float2* bd = bandp + buf * 336;
        float mx0 = -1e30f, mx1 = -1e30f;
#pragma unroll
        for (int nt = 0; nt < 8; nt++) {
            float2 b0v = bd[e0 - 8*nt];
            float2 b1v = bd[e0 + 8 - 8*nt];
            s[nt][0] += b0v.x;  s[nt][1] += b0v.y;
            s[nt][2] += b1v.x;  s[nt][3] += b1v.y;
            mx0 = fmaxf(mx0, fmaxf(s[nt][0], s[nt][1]));
            mx1 = fmaxf(mx1, fmaxf(s[nt][2], s[nt][3]));
        }
        mx0 = fmaxf(mx0, __shfl_xor_sync(0xffffffffu, mx0, 1));
        mx0 = fmaxf(mx0, __shfl_xor_sync(0xffffffffu, mx0, 2));
        mx1 = fmaxf(mx1, __shfl_xor_sync(0xffffffffu, mx1, 1));
        mx1 = fmaxf(mx1, __shfl_xor_sync(0xffffffffu, mx1, 2));
        float mn0 = fmaxf(rm0, mx0), mn1 = fmaxf(rm1, mx1);
        float a0 = rm0 - mn0, a1 = rm1 - mn1;
        float sc0, sc1;
        EX2(sc0, a0);
        EX2(sc1, a1);
        float su0 = 0.f, su1 = 0.f;
#pragma unroll
        for (int nt = 0; nt < 8; nt++) {
            float d0 = s[nt][0] - mn0, d1 = s[nt][1] - mn0;
            float d2 = s[nt][2] - mn1, d3 = s[nt][3] - mn1;
            EX2(s[nt][0], d0);
            EX2(s[nt][1], d1);
            EX2(s[nt][2], d2);
            EX2(s[nt][3], d3);
            su0 += s[nt][0] + s[nt][1];
            su1 += s[nt][2] + s[nt][3];
        }
        su0 += __shfl_xor_sync(0xffffffffu, su0, 1);
        su0 += __shfl_xor_sync(0xffffffffu, su0, 2);
        su1 += __shfl_xor_sync(0xffffffffu, su1, 1);
        su1 += __shfl_xor_sync(0xffffffffu, su1, 2);
        rl0 = rl0 * sc0 + su0;  rm0 = mn0;
        rl1 = rl1 * sc1 + su1;  rm1 = mn1;
#pragma unroll
        for (int nt = 0; nt < 8; nt++) {
            o[nt][0] *= sc0; o[nt][1] *= sc0;
            o[nt][2] *= sc1; o[nt][3] *= sc1;
        }

        // ---- O += P V  (P repacked in registers, 3-term split) ----
#pragma unroll
        for (int st = 0; st < 4; st++) {
            uint32_t ph0, ph1, ph2, ph3, pl0, pl1, pl2, pl3;
            CVT_HILO(s[2*st][0],   s[2*st][1],   ph0, pl0);
            CVT_HILO(s[2*st][2],   s[2*st][3],   ph1, pl1);
            CVT_HILO(s[2*st+1][0], s[2*st+1][1], ph2, pl2);
            CVT_HILO(s[2*st+1][2], s[2*st+1][3], ph3, pl3);
#pragma unroll
            for (int p2 = 0; p2 < 4; p2++) {
                uint32_t v0,v1,v2,v3, w0,w1,w2,w3;
                uint32_t va = sVhi + (st*16 + vrow_lane) * RS_F + (p2*2 + vcol) * 16;
                LDM_X4T(v0, v1, v2, v3, va);
                LDM_X4T(w0, w1, w2, w3, va + KVT_B);
                MMA_BF16(o[2*p2][0],o[2*p2][1],o[2*p2][2],o[2*p2][3],
                         ph0,ph1,ph2,ph3, v0,v1);
                MMA_BF16(o[2*p2][0],o[2*p2][1],o[2*p2][2],o[2*p2][3],
                         ph0,ph1,ph2,ph3, w0,w1);
                MMA_BF16(o[2*p2][0],o[2*p2][1],o[2*p2][2],o[2*p2][3],
                         pl0,pl1,pl2,pl3, v0,v1);
                MMA_BF16(o[2*p2+1][0],o[2*p2+1][1],o[2*p2+1][2],o[2*p2+1][3],
                         ph0,ph1,ph2,ph3, v2,v3);
                MMA_BF16(o[2*p2+1][0],o[2*p2+1][1],o[2*p2+1][2],o[2*p2+1][3],
                         ph0,ph1,ph2,ph3, w2,w3);
                MMA_BF16(o[2*p2+1][0],o[2*p2+1][1],o[2*p2+1][2],o[2*p2+1][3],
                         pl0,pl1,pl2,pl3, v2,v3);
            }
        }
    }

    // ---- normalize + write ctx (fp32) ----
    {
        float inv0 = 1.f / rl0, inv1 = 1.f / rl1;
        int t0 = q0 + wid*16 + g, t1 = t0 + 8;
        float* c0p = g_ctx + (long)(b * NT + t0) * NC + h * DHD + t2;
        float* c1p = g_ctx + (long)(b * NT + t1) * NC + h * DHD + t2;
#pragma unroll
        for (int nt = 0; nt < 8; nt++) {
            float2 u0 = {o[nt][0] * inv0, o[nt][1] * inv0};
            float2 u1 = {o[nt][2] * inv1, o[nt][3] * inv1};
            *(float2*)(c0p + nt * 8) = u0;
            *(float2*)(c1p + nt * 8) = u1;
        }
    }
#undef CP_STAGE
#undef BAND_W
}

// ---------------- launch ---------------------------------------------------------
extern "C" void kernel_launch(void* const* d_in, const int* in_sizes, int n_in,
                              void* d_out, int out_size)
{
    const float* x     = (const float*)d_in[0];
    const float* w_qkv = (const float*)d_in[1];
    const float* b_qkv = (const float*)d_in[2];
    const float* w_out = (const float*)d_in[3];
    const float* b_out = (const float*)d_in[4];
    const float* w1    = (const float*)d_in[5];
    const float* b1    = (const float*)d_in[6];
    const float* w2    = (const float*)d_in[7];
    const float* b2    = (const float*)d_in[8];
    float* out = (float*)d_out;

    cudaFuncSetAttribute(flash_kernel, cudaFuncAttributeMaxDynamicSharedMemorySize,
                         FL_SMEM);
    cudaFuncSetAttribute(mm_kernel<0>, cudaFuncAttributeMaxDynamicSharedMemorySize,
                         MM_SMEM_BYTES);
    cudaFuncSetAttribute(mm_kernel<1>, cudaFuncAttributeMaxDynamicSharedMemorySize,
                         MM_SMEM_BYTES);

    rpe_kernel<<<(NDIST + 255) / 256, 256>>>(w1, b1, w2, b2);

    // x -> bf16 hi/lo into g_ctx scratch (dead until flash writes it)
    conv_x_kernel<<<NM * NC / 4 / 256, 256>>>(x);

    {   // QKV projection (A = pre-converted bf16 via cp.async)
        dim3 gq(N3C / BN, NM / BM);
        mm_kernel<0><<<gq, 256, MM_SMEM_BYTES>>>(x, w_qkv, N3C, b_qkv, nullptr);
    }
    {   // flash attention (16 warps)
        dim3 gf(NT / 256, NB * NH);
        flash_kernel<<<gf, 512, FL_SMEM>>>();
    }
    {   // output projection
        dim3 go(NC / BN, NM / BM);
        mm_kernel<1><<<go, 256, MM_SMEM_BYTES>>>(nullptr, w_out, NC, b_out, out);
    }
}